// round 6
// baseline (speedup 1.0000x reference)
#include <cuda_runtime.h>
#include <cuda_bf16.h>
#include <math.h>
#include <stdint.h>

// Problem constants
#define BATCH 2
#define SEQ   2048
#define DMODEL 1024
#define NHEADS 16
#define DK    64
#define MTOT  (BATCH*SEQ)          // 4096
#define QKV_N (3*DMODEL)           // 3072
#define KEXT  (3*DMODEL)           // 3072 extended-K for bf16 split

// Scratch (device globals — no allocation allowed)
__device__ float g_qkv[(size_t)MTOT * QKV_N];             // f32 qkv
__device__ __nv_bfloat16 g_xe   [(size_t)MTOT  * KEXT];   // x extended   (A: hi,lo,hi)
__device__ __nv_bfloat16 g_wqkve[(size_t)QKV_N * KEXT];   // W_qkv ext    (B: hi,hi,lo)
__device__ __nv_bfloat16 g_wute [(size_t)DMODEL* KEXT];   // W_out ext    (B)
__device__ __nv_bfloat16 g_atte [(size_t)MTOT  * KEXT];   // attention out ext (A)

// ---------------------------------------------------------------------------
// helpers
// ---------------------------------------------------------------------------
__device__ __forceinline__ void pack_hilo(float a, float b, uint32_t& hi, uint32_t& lo)
{
    __nv_bfloat16 ha = __float2bfloat16_rn(a), hb = __float2bfloat16_rn(b);
    __nv_bfloat162 h; h.x = ha; h.y = hb;
    __nv_bfloat162 l;
    l.x = __float2bfloat16_rn(a - __bfloat162float(ha));
    l.y = __float2bfloat16_rn(b - __bfloat162float(hb));
    hi = *(uint32_t*)&h; lo = *(uint32_t*)&l;
}

__device__ __forceinline__ void ldm_x4(uint32_t& r0, uint32_t& r1, uint32_t& r2, uint32_t& r3,
                                       uint32_t addr)
{
    asm volatile("ldmatrix.sync.aligned.m8n8.x4.shared.b16 {%0,%1,%2,%3}, [%4];"
                 : "=r"(r0), "=r"(r1), "=r"(r2), "=r"(r3) : "r"(addr));
}

__device__ __forceinline__ void ldm_x4_t(uint32_t& r0, uint32_t& r1, uint32_t& r2, uint32_t& r3,
                                         uint32_t addr)
{
    asm volatile("ldmatrix.sync.aligned.m8n8.x4.trans.shared.b16 {%0,%1,%2,%3}, [%4];"
                 : "=r"(r0), "=r"(r1), "=r"(r2), "=r"(r3) : "r"(addr));
}

__device__ __forceinline__ void mma16816(float* d, const uint32_t* a, const uint32_t* b)
{
    asm volatile(
        "mma.sync.aligned.m16n8k16.row.col.f32.bf16.bf16.f32 "
        "{%0,%1,%2,%3}, {%4,%5,%6,%7}, {%8,%9}, {%0,%1,%2,%3};"
        : "+f"(d[0]), "+f"(d[1]), "+f"(d[2]), "+f"(d[3])
        : "r"(a[0]), "r"(a[1]), "r"(a[2]), "r"(a[3]), "r"(b[0]), "r"(b[1]));
}

__device__ __forceinline__ void cp16(uint32_t saddr, const void* gptr)
{
    asm volatile("cp.async.cg.shared.global [%0], [%1], 16;" :: "r"(saddr), "l"(gptr));
}

__device__ __forceinline__ void cvt_store8(__nv_bfloat16* dhi, __nv_bfloat16* dlo,
                                           float4 f0, float4 f1)
{
    uint32_t h0,h1,h2,h3,l0,l1,l2,l3;
    pack_hilo(f0.x, f0.y, h0, l0);
    pack_hilo(f0.z, f0.w, h1, l1);
    pack_hilo(f1.x, f1.y, h2, l2);
    pack_hilo(f1.z, f1.w, h3, l3);
    *(uint4*)dhi = make_uint4(h0, h1, h2, h3);
    *(uint4*)dlo = make_uint4(l0, l1, l2, l3);
}

// ---------------------------------------------------------------------------
// Split-conversion kernels: f32 [R,K] -> bf16 [R,3K]
//  A mode: [k]=hi [K+k]=lo [2K+k]=hi ;  B mode: [k]=hi [K+k]=hi [2K+k]=lo
// ---------------------------------------------------------------------------
template<int ISA>
__global__ void conv_split(const float* __restrict__ in, __nv_bfloat16* __restrict__ out,
                           int K, size_t total)
{
    size_t idx = ((size_t)blockIdx.x * blockDim.x + threadIdx.x) * 4;
    if (idx >= total) return;
    int r = (int)(idx / K);
    int k = (int)(idx % K);
    float4 v = *(const float4*)(in + idx);
    uint32_t hi01, hi23, lo01, lo23;
    pack_hilo(v.x, v.y, hi01, lo01);
    pack_hilo(v.z, v.w, hi23, lo23);
    __nv_bfloat16* o = out + (size_t)r * (3 * K) + k;
    *(uint32_t*)(o + 0) = hi01;  *(uint32_t*)(o + 2) = hi23;
    if (ISA) {
        *(uint32_t*)(o + K + 0)     = lo01; *(uint32_t*)(o + K + 2)     = lo23;
        *(uint32_t*)(o + 2 * K + 0) = hi01; *(uint32_t*)(o + 2 * K + 2) = hi23;
    } else {
        *(uint32_t*)(o + K + 0)     = hi01; *(uint32_t*)(o + K + 2)     = hi23;
        *(uint32_t*)(o + 2 * K + 0) = lo01; *(uint32_t*)(o + 2 * K + 2) = lo23;
    }
}

// ---------------------------------------------------------------------------
// bf16 tensor-core GEMM, 64x64 warp tiles: C[M,N] f32 = A[M,KEXT] * B[N,KEXT]^T
// Block tile: (WM*64) x (WN*64), BK=32, WM*WN warps.
// mma.sync.m16n8k16, ldmatrix, cp.async double buffer, XOR-swizzled smem.
// ---------------------------------------------------------------------------
template<int WM, int WN>
__global__ void __launch_bounds__(WM*WN*32, 1) gemm_ws(
    const __nv_bfloat16* __restrict__ A, const __nv_bfloat16* __restrict__ B,
    float* __restrict__ C, int N)
{
    constexpr int BM = WM * 64;
    constexpr int BN = WN * 64;
    constexpr int NT = WM * WN * 32;        // threads
    constexpr int AE = BM * 32;             // A elems / stage
    constexpr int BE = BN * 32;             // B elems / stage
    constexpr int CA = BM * 4;              // A 16B chunks / stage
    constexpr int CB = BN * 4;              // B 16B chunks / stage
    constexpr int IA = CA / NT;             // A chunks per thread
    constexpr int IB = CB / NT;

    __shared__ __nv_bfloat16 As[2][AE];
    __shared__ __nv_bfloat16 Bs[2][BE];

    const int tid  = threadIdx.x;
    const int lane = tid & 31;
    const int warp = tid >> 5;
    const int wr = warp / WN;               // 0..WM-1 -> m offset wr*64
    const int wc = warp % WN;               // 0..WN-1 -> n offset wc*64
    const int mBase = blockIdx.y * BM;
    const int nBase = blockIdx.x * BN;

    const uint32_t sA = (uint32_t)__cvta_generic_to_shared(&As[0][0]);
    const uint32_t sB = (uint32_t)__cvta_generic_to_shared(&Bs[0][0]);

    // load mapping: chunk c -> row c>>2, seg c&3; thread handles c = tid + i*NT
    const int lrow = tid >> 2;
    const int lseg = tid & 3;
    uint32_t swzA[IA], swzB[IB];
#pragma unroll
    for (int i = 0; i < IA; i++) {
        int r = lrow + i * (NT >> 2);
        swzA[i] = (uint32_t)(r * 32 + ((lseg ^ ((r >> 1) & 3)) * 8)) * 2;
    }
#pragma unroll
    for (int i = 0; i < IB; i++) {
        int r = lrow + i * (NT >> 2);
        swzB[i] = (uint32_t)(r * 32 + ((lseg ^ ((r >> 1) & 3)) * 8)) * 2;
    }
    const __nv_bfloat16* gA = A + (size_t)(mBase + lrow) * KEXT + lseg * 8;
    const __nv_bfloat16* gB = B + (size_t)(nBase + lrow) * KEXT + lseg * 8;

    // ldmatrix lane mapping
    const int arow = wr * 64 + (lane & 15);
    const int aseg = (lane >> 4) & 1;
    const int brow = wc * 64 + (lane & 7) + (((lane >> 4) & 1) << 3);
    const int bseg = (lane >> 3) & 1;

    float acc[4][8][4];
#pragma unroll
    for (int a = 0; a < 4; a++)
#pragma unroll
        for (int n = 0; n < 8; n++)
#pragma unroll
            for (int i = 0; i < 4; i++) acc[a][n][i] = 0.f;

    const int NTILES = KEXT / 32;   // 96

    // prologue
#pragma unroll
    for (int i = 0; i < IA; i++) cp16(sA + swzA[i], gA + (size_t)i * (NT >> 2) * KEXT);
#pragma unroll
    for (int i = 0; i < IB; i++) cp16(sB + swzB[i], gB + (size_t)i * (NT >> 2) * KEXT);
    asm volatile("cp.async.commit_group;");

    for (int t = 0; t < NTILES; t++) {
        if (t + 1 < NTILES) {
            const int k0 = (t + 1) * 32;
            const uint32_t soA = ((t + 1) & 1) * (AE * 2);
            const uint32_t soB = ((t + 1) & 1) * (BE * 2);
#pragma unroll
            for (int i = 0; i < IA; i++)
                cp16(sA + soA + swzA[i], gA + (size_t)i * (NT >> 2) * KEXT + k0);
#pragma unroll
            for (int i = 0; i < IB; i++)
                cp16(sB + soB + swzB[i], gB + (size_t)i * (NT >> 2) * KEXT + k0);
            asm volatile("cp.async.commit_group;");
            asm volatile("cp.async.wait_group 1;");
        } else {
            asm volatile("cp.async.wait_group 0;");
        }
        __syncthreads();

        const uint32_t aBase = sA + (t & 1) * (AE * 2);
        const uint32_t bBase = sB + (t & 1) * (BE * 2);

#pragma unroll
        for (int kk = 0; kk < 2; kk++) {
            uint32_t af[4][4];
#pragma unroll
            for (int a = 0; a < 4; a++) {
                int r = arow + a * 16;
                int seg = (kk * 2 + aseg) ^ ((r >> 1) & 3);
                ldm_x4(af[a][0], af[a][1], af[a][2], af[a][3],
                       aBase + (uint32_t)(r * 32 + seg * 8) * 2);
            }
            uint32_t bf[8][2];
#pragma unroll
            for (int p = 0; p < 4; p++) {
                int n = brow + p * 16;
                int seg = (kk * 2 + bseg) ^ ((n >> 1) & 3);
                uint32_t r0, r1, r2, r3;
                ldm_x4(r0, r1, r2, r3, bBase + (uint32_t)(n * 32 + seg * 8) * 2);
                bf[p * 2 + 0][0] = r0; bf[p * 2 + 0][1] = r1;
                bf[p * 2 + 1][0] = r2; bf[p * 2 + 1][1] = r3;
            }
#pragma unroll
            for (int a = 0; a < 4; a++)
#pragma unroll
                for (int n = 0; n < 8; n++)
                    mma16816(acc[a][n], af[a], bf[n]);
        }
        __syncthreads();
    }

    // epilogue
#pragma unroll
    for (int a = 0; a < 4; a++) {
        int row0 = mBase + wr * 64 + a * 16 + (lane >> 2);
#pragma unroll
        for (int n = 0; n < 8; n++) {
            int col = nBase + wc * 64 + n * 8 + (lane & 3) * 2;
            *(float2*)&C[(size_t)row0 * N + col]       = make_float2(acc[a][n][0], acc[a][n][1]);
            *(float2*)&C[(size_t)(row0 + 8) * N + col] = make_float2(acc[a][n][2], acc[a][n][3]);
        }
    }
}

// ---------------------------------------------------------------------------
// Tensor-core causal flash attention with bf16 hi/lo split (unchanged, R4).
// ---------------------------------------------------------------------------
__global__ void __launch_bounds__(256, 1) attn_tc(
    const float* __restrict__ qkv, __nv_bfloat16* __restrict__ atte)
{
    extern __shared__ __nv_bfloat16 sm[];
    const uint32_t sbase = (uint32_t)__cvta_generic_to_shared(sm);

    const int b = blockIdx.z, h = blockIdx.y;
    const int qt = (int)(gridDim.x - 1 - blockIdx.x);
    const int q0 = qt * 128;
    const int tid = threadIdx.x;
    const int lane = tid & 31, warp = tid >> 5;

    for (int e = tid; e < 1024; e += 256) {
        int r = e >> 3, sg = e & 7;
        const float* gq = qkv + ((size_t)(b * SEQ + q0 + r)) * QKV_N + h * DK + sg * 8;
        float4 f0 = *(const float4*)gq;
        float4 f1 = *(const float4*)(gq + 4);
        f0.x *= 0.125f; f0.y *= 0.125f; f0.z *= 0.125f; f0.w *= 0.125f;
        f1.x *= 0.125f; f1.y *= 0.125f; f1.z *= 0.125f; f1.w *= 0.125f;
        int off = r * 64 + ((sg ^ (r & 7)) * 8);
        cvt_store8(sm + off, sm + 8192 + off, f0, f1);
    }
    __syncthreads();

    uint32_t qh[4][4], ql[4][4];
    {
        const int r = warp * 16 + (lane & 15);
        const int sgx = lane >> 4;
#pragma unroll
        for (int ks = 0; ks < 4; ks++) {
            int sg = (2 * ks + sgx) ^ (r & 7);
            uint32_t ad = sbase + (uint32_t)(r * 64 + sg * 8) * 2;
            ldm_x4(qh[ks][0], qh[ks][1], qh[ks][2], qh[ks][3], ad);
            ldm_x4(ql[ks][0], ql[ks][1], ql[ks][2], ql[ks][3], ad + 16384);
        }
    }

    float o[8][4];
#pragma unroll
    for (int t = 0; t < 8; t++) { o[t][0]=0.f; o[t][1]=0.f; o[t][2]=0.f; o[t][3]=0.f; }
    float m0 = -1e30f, m1 = -1e30f, l0 = 0.f, l1 = 0.f;

    const int ktmax = q0 / 64 + 1;
    for (int kt = 0; kt <= ktmax; kt++) {
        const int kbase = kt * 64;
        __syncthreads();
        for (int e = tid; e < 512; e += 256) {
            int r = e >> 3, sg = e & 7;
            size_t g = ((size_t)(b * SEQ + kbase + r)) * QKV_N + h * DK + sg * 8;
            int off = r * 64 + ((sg ^ (r & 7)) * 8);
            float4 k0 = *(const float4*)(qkv + g + DMODEL);
            float4 k1 = *(const float4*)(qkv + g + DMODEL + 4);
            cvt_store8(sm + off,        sm + 4096 + off,  k0, k1);
            float4 v0 = *(const float4*)(qkv + g + 2 * DMODEL);
            float4 v1 = *(const float4*)(qkv + g + 2 * DMODEL + 4);
            cvt_store8(sm + 8192 + off, sm + 12288 + off, v0, v1);
        }
        __syncthreads();

        if (kbase <= q0 + warp * 16 + 15) {
            float s[8][4];
#pragma unroll
            for (int t = 0; t < 8; t++) { s[t][0]=0.f; s[t][1]=0.f; s[t][2]=0.f; s[t][3]=0.f; }

#pragma unroll
            for (int kk = 0; kk < 4; kk++) {
#pragma unroll
                for (int np = 0; np < 4; np++) {
                    int krow = np * 16 + (lane & 7) + (((lane >> 4) & 1) << 3);
                    int ksg = (2 * kk + ((lane >> 3) & 1)) ^ (krow & 7);
                    uint32_t ad = sbase + (uint32_t)(krow * 64 + ksg * 8) * 2;
                    uint32_t bh0, bh1, bh2, bh3, bl0, bl1, bl2, bl3;
                    ldm_x4(bh0, bh1, bh2, bh3, ad);
                    ldm_x4(bl0, bl1, bl2, bl3, ad + 8192);
                    uint32_t bb[2];
                    bb[0] = bh0; bb[1] = bh1;
                    mma16816(s[2*np],   qh[kk], bb);
                    mma16816(s[2*np],   ql[kk], bb);
                    bb[0] = bh2; bb[1] = bh3;
                    mma16816(s[2*np+1], qh[kk], bb);
                    mma16816(s[2*np+1], ql[kk], bb);
                    bb[0] = bl0; bb[1] = bl1;
                    mma16816(s[2*np],   qh[kk], bb);
                    bb[0] = bl2; bb[1] = bl3;
                    mma16816(s[2*np+1], qh[kk], bb);
                }
            }

            const int rg0 = q0 + warp * 16 + (lane >> 2);
            if (kbase + 63 > q0 + warp * 16) {
#pragma unroll
                for (int nt = 0; nt < 8; nt++) {
                    int c0 = kbase + nt * 8 + 2 * (lane & 3);
                    if (c0     > rg0)     s[nt][0] = -1e30f;
                    if (c0 + 1 > rg0)     s[nt][1] = -1e30f;
                    if (c0     > rg0 + 8) s[nt][2] = -1e30f;
                    if (c0 + 1 > rg0 + 8) s[nt][3] = -1e30f;
                }
            }

            float mx0 = -1e30f, mx1 = -1e30f;
#pragma unroll
            for (int nt = 0; nt < 8; nt++) {
                mx0 = fmaxf(mx0, fmaxf(s[nt][0], s[nt][1]));
                mx1 = fmaxf(mx1, fmaxf(s[nt][2], s[nt][3]));
            }
            mx0 = fmaxf(mx0, __shfl_xor_sync(0xffffffffu, mx0, 1));
            mx0 = fmaxf(mx0, __shfl_xor_sync(0xffffffffu, mx0, 2));
            mx1 = fmaxf(mx1, __shfl_xor_sync(0xffffffffu, mx1, 1));
            mx1 = fmaxf(mx1, __shfl_xor_sync(0xffffffffu, mx1, 2));
            float mn0 = fmaxf(m0, mx0), mn1 = fmaxf(m1, mx1);
            float cr0 = __expf(m0 - mn0), cr1 = __expf(m1 - mn1);
            m0 = mn0; m1 = mn1;
            float sum0 = 0.f, sum1 = 0.f;
#pragma unroll
            for (int nt = 0; nt < 8; nt++) {
                s[nt][0] = __expf(s[nt][0] - mn0);
                s[nt][1] = __expf(s[nt][1] - mn0);
                s[nt][2] = __expf(s[nt][2] - mn1);
                s[nt][3] = __expf(s[nt][3] - mn1);
                sum0 += s[nt][0] + s[nt][1];
                sum1 += s[nt][2] + s[nt][3];
            }
            sum0 += __shfl_xor_sync(0xffffffffu, sum0, 1);
            sum0 += __shfl_xor_sync(0xffffffffu, sum0, 2);
            sum1 += __shfl_xor_sync(0xffffffffu, sum1, 1);
            sum1 += __shfl_xor_sync(0xffffffffu, sum1, 2);
            l0 = l0 * cr0 + sum0;
            l1 = l1 * cr1 + sum1;
#pragma unroll
            for (int t = 0; t < 8; t++) {
                o[t][0] *= cr0; o[t][1] *= cr0; o[t][2] *= cr1; o[t][3] *= cr1;
            }

#pragma unroll
            for (int ks = 0; ks < 4; ks++) {
                uint32_t ah[4], al[4];
                pack_hilo(s[2*ks][0],   s[2*ks][1],   ah[0], al[0]);
                pack_hilo(s[2*ks][2],   s[2*ks][3],   ah[1], al[1]);
                pack_hilo(s[2*ks+1][0], s[2*ks+1][1], ah[2], al[2]);
                pack_hilo(s[2*ks+1][2], s[2*ks+1][3], ah[3], al[3]);
#pragma unroll
                for (int cp = 0; cp < 4; cp++) {
                    int vrow = ks * 16 + (lane & 15);
                    int vsg = (2 * cp + (lane >> 4)) ^ (vrow & 7);
                    uint32_t va = sbase + 16384 + (uint32_t)(vrow * 64 + vsg * 8) * 2;
                    uint32_t vh0, vh1, vh2, vh3, vl0, vl1, vl2, vl3;
                    ldm_x4_t(vh0, vh1, vh2, vh3, va);
                    ldm_x4_t(vl0, vl1, vl2, vl3, va + 8192);
                    uint32_t bb[2];
                    bb[0] = vh0; bb[1] = vh1;
                    mma16816(o[2*cp],   ah, bb);
                    mma16816(o[2*cp],   al, bb);
                    bb[0] = vl0; bb[1] = vl1;
                    mma16816(o[2*cp],   ah, bb);
                    bb[0] = vh2; bb[1] = vh3;
                    mma16816(o[2*cp+1], ah, bb);
                    mma16816(o[2*cp+1], al, bb);
                    bb[0] = vl2; bb[1] = vl3;
                    mma16816(o[2*cp+1], ah, bb);
                }
            }
        }
    }

    const float inv0 = 1.f / l0, inv1 = 1.f / l1;
    const int rg0 = q0 + warp * 16 + (lane >> 2);
    const size_t ro0 = (size_t)(b * SEQ + rg0) * KEXT;
    const size_t ro1 = (size_t)(b * SEQ + rg0 + 8) * KEXT;
#pragma unroll
    for (int nt = 0; nt < 8; nt++) {
        int col = h * DK + nt * 8 + 2 * (lane & 3);
        uint32_t hi, lo;
        pack_hilo(o[nt][0] * inv0, o[nt][1] * inv0, hi, lo);
        *(uint32_t*)(atte + ro0 + col)            = hi;
        *(uint32_t*)(atte + ro0 + DMODEL + col)   = lo;
        *(uint32_t*)(atte + ro0 + 2*DMODEL + col) = hi;
        pack_hilo(o[nt][2] * inv1, o[nt][3] * inv1, hi, lo);
        *(uint32_t*)(atte + ro1 + col)            = hi;
        *(uint32_t*)(atte + ro1 + DMODEL + col)   = lo;
        *(uint32_t*)(atte + ro1 + 2*DMODEL + col) = hi;
    }
}

// ---------------------------------------------------------------------------
// kernel_launch
// ---------------------------------------------------------------------------
extern "C" void kernel_launch(void* const* d_in, const int* in_sizes, int n_in,
                              void* d_out, int out_size)
{
    const float* x     = (const float*)d_in[0];   // [2, 2048, 1024]
    const float* W_qkv = (const float*)d_in[1];   // [3072, 1024]
    const float* W_out = (const float*)d_in[2];   // [1024, 1024]
    float* out = (float*)d_out;                   // [2, 2048, 1024]

    float* qkv_ptr = nullptr;
    __nv_bfloat16 *xe, *wqkve, *wute, *atte;
    cudaGetSymbolAddress((void**)&qkv_ptr, g_qkv);
    cudaGetSymbolAddress((void**)&xe,    g_xe);
    cudaGetSymbolAddress((void**)&wqkve, g_wqkve);
    cudaGetSymbolAddress((void**)&wute,  g_wute);
    cudaGetSymbolAddress((void**)&atte,  g_atte);

    cudaFuncSetAttribute(attn_tc, cudaFuncAttributeMaxDynamicSharedMemorySize, 32768);

    // 0) split conversions (inputs)
    {
        size_t tx_ = (size_t)MTOT * DMODEL;
        conv_split<1><<<(unsigned)((tx_/4 + 255)/256), 256>>>(x, xe, DMODEL, tx_);
        size_t tw = (size_t)QKV_N * DMODEL;
        conv_split<0><<<(unsigned)((tw/4 + 255)/256), 256>>>(W_qkv, wqkve, DMODEL, tw);
        size_t tu = (size_t)DMODEL * DMODEL;
        conv_split<0><<<(unsigned)((tu/4 + 255)/256), 256>>>(W_out, wute, DMODEL, tu);
    }
    // 1) QKV projection: 256x128 block, 8 warps -> [4096,3072] f32
    {
        dim3 grid(QKV_N / 128, MTOT / 256);   // (24,16)
        gemm_ws<4,2><<<grid, 256>>>(xe, wqkve, qkv_ptr, QKV_N);
    }
    // 2) tensor-core causal flash attention -> g_atte (bf16 split layout)
    {
        dim3 grid(SEQ / 128, NHEADS, BATCH);
        attn_tc<<<grid, 256, 32768>>>(qkv_ptr, atte);
    }
    // 3) output projection: 128x128 block, 4 warps -> d_out
    {
        dim3 grid(DMODEL / 128, MTOT / 128);  // (8,32)
        gemm_ws<2,2><<<grid, 128>>>(atte, wute, out, DMODEL);
    }
}

// round 7
// speedup vs baseline: 1.1875x; 1.1875x over previous
#include <cuda_runtime.h>
#include <cuda_bf16.h>
#include <math.h>
#include <stdint.h>

// Problem constants
#define BATCH 2
#define SEQ   2048
#define DMODEL 1024
#define NHEADS 16
#define DK    64
#define MTOT  (BATCH*SEQ)          // 4096
#define QKV_N (3*DMODEL)           // 3072
#define KEXT  (3*DMODEL)           // 3072 extended-K for bf16 split

// Scratch (device globals — no allocation allowed)
__device__ float g_qkv[(size_t)MTOT * QKV_N];             // f32 qkv
__device__ __nv_bfloat16 g_xe   [(size_t)MTOT  * KEXT];   // x extended   (A: hi,lo,hi)
__device__ __nv_bfloat16 g_wqkve[(size_t)QKV_N * KEXT];   // W_qkv ext    (B: hi,hi,lo)
__device__ __nv_bfloat16 g_wute [(size_t)DMODEL* KEXT];   // W_out ext    (B)
__device__ __nv_bfloat16 g_atte [(size_t)MTOT  * KEXT];   // attention out ext (A)
// pre-converted K/V, layout [b][h][s][dk] bf16
__device__ __nv_bfloat16 g_khe[(size_t)MTOT * DMODEL];
__device__ __nv_bfloat16 g_kle[(size_t)MTOT * DMODEL];
__device__ __nv_bfloat16 g_vhe[(size_t)MTOT * DMODEL];
__device__ __nv_bfloat16 g_vle[(size_t)MTOT * DMODEL];

// ---------------------------------------------------------------------------
// helpers
// ---------------------------------------------------------------------------
__device__ __forceinline__ void pack_hilo(float a, float b, uint32_t& hi, uint32_t& lo)
{
    __nv_bfloat16 ha = __float2bfloat16_rn(a), hb = __float2bfloat16_rn(b);
    __nv_bfloat162 h; h.x = ha; h.y = hb;
    __nv_bfloat162 l;
    l.x = __float2bfloat16_rn(a - __bfloat162float(ha));
    l.y = __float2bfloat16_rn(b - __bfloat162float(hb));
    hi = *(uint32_t*)&h; lo = *(uint32_t*)&l;
}

__device__ __forceinline__ void ldm_x4(uint32_t& r0, uint32_t& r1, uint32_t& r2, uint32_t& r3,
                                       uint32_t addr)
{
    asm volatile("ldmatrix.sync.aligned.m8n8.x4.shared.b16 {%0,%1,%2,%3}, [%4];"
                 : "=r"(r0), "=r"(r1), "=r"(r2), "=r"(r3) : "r"(addr));
}

__device__ __forceinline__ void ldm_x4_t(uint32_t& r0, uint32_t& r1, uint32_t& r2, uint32_t& r3,
                                         uint32_t addr)
{
    asm volatile("ldmatrix.sync.aligned.m8n8.x4.trans.shared.b16 {%0,%1,%2,%3}, [%4];"
                 : "=r"(r0), "=r"(r1), "=r"(r2), "=r"(r3) : "r"(addr));
}

__device__ __forceinline__ void mma16816(float* d, const uint32_t* a, const uint32_t* b)
{
    asm volatile(
        "mma.sync.aligned.m16n8k16.row.col.f32.bf16.bf16.f32 "
        "{%0,%1,%2,%3}, {%4,%5,%6,%7}, {%8,%9}, {%0,%1,%2,%3};"
        : "+f"(d[0]), "+f"(d[1]), "+f"(d[2]), "+f"(d[3])
        : "r"(a[0]), "r"(a[1]), "r"(a[2]), "r"(a[3]), "r"(b[0]), "r"(b[1]));
}

__device__ __forceinline__ void cp16(uint32_t saddr, const void* gptr)
{
    asm volatile("cp.async.cg.shared.global [%0], [%1], 16;" :: "r"(saddr), "l"(gptr));
}

__device__ __forceinline__ void cvt_store8(__nv_bfloat16* dhi, __nv_bfloat16* dlo,
                                           float4 f0, float4 f1)
{
    uint32_t h0,h1,h2,h3,l0,l1,l2,l3;
    pack_hilo(f0.x, f0.y, h0, l0);
    pack_hilo(f0.z, f0.w, h1, l1);
    pack_hilo(f1.x, f1.y, h2, l2);
    pack_hilo(f1.z, f1.w, h3, l3);
    *(uint4*)dhi = make_uint4(h0, h1, h2, h3);
    *(uint4*)dlo = make_uint4(l0, l1, l2, l3);
}

// ---------------------------------------------------------------------------
// Split-conversion kernels: f32 [R,K] -> bf16 [R,3K]
// ---------------------------------------------------------------------------
template<int ISA>
__global__ void conv_split(const float* __restrict__ in, __nv_bfloat16* __restrict__ out,
                           int K, size_t total)
{
    size_t idx = ((size_t)blockIdx.x * blockDim.x + threadIdx.x) * 4;
    if (idx >= total) return;
    int r = (int)(idx / K);
    int k = (int)(idx % K);
    float4 v = *(const float4*)(in + idx);
    uint32_t hi01, hi23, lo01, lo23;
    pack_hilo(v.x, v.y, hi01, lo01);
    pack_hilo(v.z, v.w, hi23, lo23);
    __nv_bfloat16* o = out + (size_t)r * (3 * K) + k;
    *(uint32_t*)(o + 0) = hi01;  *(uint32_t*)(o + 2) = hi23;
    if (ISA) {
        *(uint32_t*)(o + K + 0)     = lo01; *(uint32_t*)(o + K + 2)     = lo23;
        *(uint32_t*)(o + 2 * K + 0) = hi01; *(uint32_t*)(o + 2 * K + 2) = hi23;
    } else {
        *(uint32_t*)(o + K + 0)     = hi01; *(uint32_t*)(o + K + 2)     = hi23;
        *(uint32_t*)(o + 2 * K + 0) = lo01; *(uint32_t*)(o + 2 * K + 2) = lo23;
    }
}

// ---------------------------------------------------------------------------
// conv_qkv: pre-convert K and V slabs of g_qkv to hi/lo bf16, [b,h,s,dk].
// Row r in [0,MTOT), col c in [0,DMODEL): reads qkv[r][1024+c] (K), [2048+c] (V).
// ---------------------------------------------------------------------------
__global__ void conv_qkv(const float* __restrict__ qkv)
{
    size_t idx = ((size_t)blockIdx.x * blockDim.x + threadIdx.x) * 4;   // over MTOT*DMODEL
    if (idx >= (size_t)MTOT * DMODEL) return;
    int r = (int)(idx >> 10);          // row in [0,4096)
    int c = (int)(idx & 1023);         // col in [0,1024)
    int h = c >> 6, d = c & 63;
    int b = r >> 11, s = r & 2047;
    size_t dst = (((size_t)(b * NHEADS + h)) * SEQ + s) * DK + d;

    const float* src = qkv + (size_t)r * QKV_N + DMODEL + c;
    float4 kv = *(const float4*)src;
    float4 vv = *(const float4*)(src + DMODEL);
    uint32_t h01, h23, l01, l23;
    pack_hilo(kv.x, kv.y, h01, l01); pack_hilo(kv.z, kv.w, h23, l23);
    *(uint32_t*)&g_khe[dst] = h01; *(uint32_t*)&g_khe[dst + 2] = h23;
    *(uint32_t*)&g_kle[dst] = l01; *(uint32_t*)&g_kle[dst + 2] = l23;
    pack_hilo(vv.x, vv.y, h01, l01); pack_hilo(vv.z, vv.w, h23, l23);
    *(uint32_t*)&g_vhe[dst] = h01; *(uint32_t*)&g_vhe[dst + 2] = h23;
    *(uint32_t*)&g_vle[dst] = l01; *(uint32_t*)&g_vle[dst + 2] = l23;
}

// ---------------------------------------------------------------------------
// bf16 tensor-core GEMM (R3/R4 config, known-good): 128x128 block, BK=32,
// 256 thr, warp tile 64x32, cp.async double buffer.
// ---------------------------------------------------------------------------
#define TILE_ELEMS (128*32)

__global__ void __launch_bounds__(256, 2) gemm_bf16(
    const __nv_bfloat16* __restrict__ A, const __nv_bfloat16* __restrict__ B,
    float* __restrict__ C, int N)
{
    __shared__ __nv_bfloat16 As[2][TILE_ELEMS];
    __shared__ __nv_bfloat16 Bs[2][TILE_ELEMS];

    const int tid  = threadIdx.x;
    const int lane = tid & 31;
    const int warp = tid >> 5;
    const int wr = warp >> 2;
    const int wc = warp & 3;
    const int mBase = blockIdx.y * 128;
    const int nBase = blockIdx.x * 128;

    const uint32_t sA = (uint32_t)__cvta_generic_to_shared(&As[0][0]);
    const uint32_t sB = (uint32_t)__cvta_generic_to_shared(&Bs[0][0]);

    const int lrow = tid >> 2;
    const int lseg = tid & 3;
    const uint32_t swz0 = (uint32_t)(lrow * 32 + ((lseg ^ ((lrow >> 1) & 3)) * 8)) * 2;
    const uint32_t swz1 = (uint32_t)((lrow + 64) * 32 + ((lseg ^ (((lrow + 64) >> 1) & 3)) * 8)) * 2;
    const __nv_bfloat16* gA0 = A + (size_t)(mBase + lrow)      * KEXT + lseg * 8;
    const __nv_bfloat16* gA1 = A + (size_t)(mBase + lrow + 64) * KEXT + lseg * 8;
    const __nv_bfloat16* gB0 = B + (size_t)(nBase + lrow)      * KEXT + lseg * 8;
    const __nv_bfloat16* gB1 = B + (size_t)(nBase + lrow + 64) * KEXT + lseg * 8;

    const int arow = wr * 64 + (lane & 15);
    const int aseg = (lane >> 4) & 1;
    const int brow = wc * 32 + (lane & 7) + (((lane >> 4) & 1) << 3);
    const int bseg = (lane >> 3) & 1;

    float acc[4][4][4];
#pragma unroll
    for (int a = 0; a < 4; a++)
#pragma unroll
        for (int n = 0; n < 4; n++)
#pragma unroll
            for (int i = 0; i < 4; i++) acc[a][n][i] = 0.f;

    const int NTILES = KEXT / 32;

    cp16(sA + swz0, gA0); cp16(sA + swz1, gA1);
    cp16(sB + swz0, gB0); cp16(sB + swz1, gB1);
    asm volatile("cp.async.commit_group;");

    for (int t = 0; t < NTILES; t++) {
        if (t + 1 < NTILES) {
            const int k0 = (t + 1) * 32;
            const uint32_t so = ((t + 1) & 1) * (TILE_ELEMS * 2);
            cp16(sA + so + swz0, gA0 + k0); cp16(sA + so + swz1, gA1 + k0);
            cp16(sB + so + swz0, gB0 + k0); cp16(sB + so + swz1, gB1 + k0);
            asm volatile("cp.async.commit_group;");
            asm volatile("cp.async.wait_group 1;");
        } else {
            asm volatile("cp.async.wait_group 0;");
        }
        __syncthreads();

        const uint32_t aBase = sA + (t & 1) * (TILE_ELEMS * 2);
        const uint32_t bBase = sB + (t & 1) * (TILE_ELEMS * 2);

#pragma unroll
        for (int kk = 0; kk < 2; kk++) {
            uint32_t af[4][4];
#pragma unroll
            for (int a = 0; a < 4; a++) {
                int r = arow + a * 16;
                int seg = (kk * 2 + aseg) ^ ((r >> 1) & 3);
                ldm_x4(af[a][0], af[a][1], af[a][2], af[a][3],
                       aBase + (uint32_t)(r * 32 + seg * 8) * 2);
            }
            uint32_t bf[4][2];
#pragma unroll
            for (int p = 0; p < 2; p++) {
                int n = brow + p * 16;
                int seg = (kk * 2 + bseg) ^ ((n >> 1) & 3);
                uint32_t r0, r1, r2, r3;
                ldm_x4(r0, r1, r2, r3, bBase + (uint32_t)(n * 32 + seg * 8) * 2);
                bf[p * 2 + 0][0] = r0; bf[p * 2 + 0][1] = r1;
                bf[p * 2 + 1][0] = r2; bf[p * 2 + 1][1] = r3;
            }
#pragma unroll
            for (int a = 0; a < 4; a++)
#pragma unroll
                for (int n = 0; n < 4; n++)
                    mma16816(acc[a][n], af[a], bf[n]);
        }
        __syncthreads();
    }

#pragma unroll
    for (int a = 0; a < 4; a++) {
        int row0 = mBase + wr * 64 + a * 16 + (lane >> 2);
#pragma unroll
        for (int n = 0; n < 4; n++) {
            int col = nBase + wc * 32 + n * 8 + (lane & 3) * 2;
            *(float2*)&C[(size_t)row0 * N + col]       = make_float2(acc[a][n][0], acc[a][n][1]);
            *(float2*)&C[(size_t)(row0 + 8) * N + col] = make_float2(acc[a][n][2], acc[a][n][3]);
        }
    }
}

// ---------------------------------------------------------------------------
// Tensor-core causal flash attention, bf16 hi/lo split, cp.async K/V pipeline.
// Block 256 thr / 8 warps; Q tile 128 rows; K tiles of 64 keys, double-buffered.
// smem: 2 stages x 32KB. Stage layout: Khi@0, Klo@8KB, Vhi@16KB, Vlo@24KB.
// Q staged temporarily in stage0 (hi@0 16KB, lo@16KB).
// ---------------------------------------------------------------------------
__global__ void __launch_bounds__(256, 1) attn_tc(
    const float* __restrict__ qkv, __nv_bfloat16* __restrict__ atte)
{
    extern __shared__ __nv_bfloat16 sm[];
    const uint32_t sbase = (uint32_t)__cvta_generic_to_shared(sm);

    const int b = blockIdx.z, h = blockIdx.y;
    const int qt = (int)(gridDim.x - 1 - blockIdx.x);   // heavy tiles first
    const int q0 = qt * 128;
    const int tid = threadIdx.x;
    const int lane = tid & 31, warp = tid >> 5;

    // global K/V bases for this (b,h)
    const size_t kvbase = ((size_t)(b * NHEADS + h)) * SEQ * DK;
    const __nv_bfloat16* mats[4] = { g_khe + kvbase, g_kle + kvbase,
                                     g_vhe + kvbase, g_vle + kvbase };

    // per-thread cp.async mapping: 8 chunks (16B each) per tile
    uint32_t dstoff[8];
    const __nv_bfloat16* srcp[8];
#pragma unroll
    for (int j = 0; j < 8; j++) {
        int c = tid + j * 256;           // 0..2047
        int m = c >> 9;                  // matrix 0..3
        int w = c & 511;
        int r = w >> 3, sg = w & 7;
        dstoff[j] = (uint32_t)(m * 8192) + (uint32_t)(r * 64 + ((sg ^ (r & 7)) * 8)) * 2;
        srcp[j] = mats[m] + r * DK + sg * 8;
    }

    // --- Stage Q (pre-scaled by 1/8) into stage0: hi@[0,16KB), lo@[16KB,32KB)
    for (int e = tid; e < 1024; e += 256) {
        int r = e >> 3, sg = e & 7;
        const float* gq = qkv + ((size_t)(b * SEQ + q0 + r)) * QKV_N + h * DK + sg * 8;
        float4 f0 = *(const float4*)gq;
        float4 f1 = *(const float4*)(gq + 4);
        f0.x *= 0.125f; f0.y *= 0.125f; f0.z *= 0.125f; f0.w *= 0.125f;
        f1.x *= 0.125f; f1.y *= 0.125f; f1.z *= 0.125f; f1.w *= 0.125f;
        int off = r * 64 + ((sg ^ (r & 7)) * 8);
        cvt_store8(sm + off, sm + 8192 + off, f0, f1);
    }
    __syncthreads();

    // prefetch tile 0 -> stage 1
#pragma unroll
    for (int j = 0; j < 8; j++) cp16(sbase + 32768 + dstoff[j], srcp[j]);
    asm volatile("cp.async.commit_group;");

    // --- Q fragments into registers (reads stage0)
    uint32_t qh[4][4], ql[4][4];
    {
        const int r = warp * 16 + (lane & 15);
        const int sgx = lane >> 4;
#pragma unroll
        for (int ks = 0; ks < 4; ks++) {
            int sg = (2 * ks + sgx) ^ (r & 7);
            uint32_t ad = sbase + (uint32_t)(r * 64 + sg * 8) * 2;
            ldm_x4(qh[ks][0], qh[ks][1], qh[ks][2], qh[ks][3], ad);
            ldm_x4(ql[ks][0], ql[ks][1], ql[ks][2], ql[ks][3], ad + 16384);
        }
    }
    __syncthreads();   // stage0 free for prefetch of tile 1

    float o[8][4];
#pragma unroll
    for (int t = 0; t < 8; t++) { o[t][0]=0.f; o[t][1]=0.f; o[t][2]=0.f; o[t][3]=0.f; }
    float m0 = -1e30f, m1 = -1e30f, l0 = 0.f, l1 = 0.f;

    const int ktmax = q0 / 64 + 1;
    for (int kt = 0; kt <= ktmax; kt++) {
        const int kbase = kt * 64;
        // prefetch tile kt+1 into stage kt&1 (freed last iteration / Q phase)
        if (kt + 1 <= ktmax) {
            const uint32_t so = (uint32_t)(kt & 1) * 32768;
            const size_t goff = (size_t)(kbase + 64) * DK;
#pragma unroll
            for (int j = 0; j < 8; j++) cp16(sbase + so + dstoff[j], srcp[j] + goff);
            asm volatile("cp.async.commit_group;");
            asm volatile("cp.async.wait_group 1;");
        } else {
            asm volatile("cp.async.wait_group 0;");
        }
        __syncthreads();
        const uint32_t sstage = sbase + (uint32_t)((kt + 1) & 1) * 32768;

        if (kbase <= q0 + warp * 16 + 15) {   // skip fully-masked warps
            float s[8][4];
#pragma unroll
            for (int t = 0; t < 8; t++) { s[t][0]=0.f; s[t][1]=0.f; s[t][2]=0.f; s[t][3]=0.f; }

#pragma unroll
            for (int kk = 0; kk < 4; kk++) {
#pragma unroll
                for (int np = 0; np < 4; np++) {
                    int krow = np * 16 + (lane & 7) + (((lane >> 4) & 1) << 3);
                    int ksg = (2 * kk + ((lane >> 3) & 1)) ^ (krow & 7);
                    uint32_t ad = sstage + (uint32_t)(krow * 64 + ksg * 8) * 2;
                    uint32_t bh0, bh1, bh2, bh3, bl0, bl1, bl2, bl3;
                    ldm_x4(bh0, bh1, bh2, bh3, ad);
                    ldm_x4(bl0, bl1, bl2, bl3, ad + 8192);
                    uint32_t bb[2];
                    bb[0] = bh0; bb[1] = bh1;
                    mma16816(s[2*np],   qh[kk], bb);
                    mma16816(s[2*np],   ql[kk], bb);
                    bb[0] = bh2; bb[1] = bh3;
                    mma16816(s[2*np+1], qh[kk], bb);
                    mma16816(s[2*np+1], ql[kk], bb);
                    bb[0] = bl0; bb[1] = bl1;
                    mma16816(s[2*np],   qh[kk], bb);
                    bb[0] = bl2; bb[1] = bl3;
                    mma16816(s[2*np+1], qh[kk], bb);
                }
            }

            const int rg0 = q0 + warp * 16 + (lane >> 2);
            if (kbase + 63 > q0 + warp * 16) {
#pragma unroll
                for (int nt = 0; nt < 8; nt++) {
                    int c0 = kbase + nt * 8 + 2 * (lane & 3);
                    if (c0     > rg0)     s[nt][0] = -1e30f;
                    if (c0 + 1 > rg0)     s[nt][1] = -1e30f;
                    if (c0     > rg0 + 8) s[nt][2] = -1e30f;
                    if (c0 + 1 > rg0 + 8) s[nt][3] = -1e30f;
                }
            }

            float mx0 = -1e30f, mx1 = -1e30f;
#pragma unroll
            for (int nt = 0; nt < 8; nt++) {
                mx0 = fmaxf(mx0, fmaxf(s[nt][0], s[nt][1]));
                mx1 = fmaxf(mx1, fmaxf(s[nt][2], s[nt][3]));
            }
            mx0 = fmaxf(mx0, __shfl_xor_sync(0xffffffffu, mx0, 1));
            mx0 = fmaxf(mx0, __shfl_xor_sync(0xffffffffu, mx0, 2));
            mx1 = fmaxf(mx1, __shfl_xor_sync(0xffffffffu, mx1, 1));
            mx1 = fmaxf(mx1, __shfl_xor_sync(0xffffffffu, mx1, 2));
            float mn0 = fmaxf(m0, mx0), mn1 = fmaxf(m1, mx1);
            float cr0 = __expf(m0 - mn0), cr1 = __expf(m1 - mn1);
            m0 = mn0; m1 = mn1;
            float sum0 = 0.f, sum1 = 0.f;
#pragma unroll
            for (int nt = 0; nt < 8; nt++) {
                s[nt][0] = __expf(s[nt][0] - mn0);
                s[nt][1] = __expf(s[nt][1] - mn0);
                s[nt][2] = __expf(s[nt][2] - mn1);
                s[nt][3] = __expf(s[nt][3] - mn1);
                sum0 += s[nt][0] + s[nt][1];
                sum1 += s[nt][2] + s[nt][3];
            }
            sum0 += __shfl_xor_sync(0xffffffffu, sum0, 1);
            sum0 += __shfl_xor_sync(0xffffffffu, sum0, 2);
            sum1 += __shfl_xor_sync(0xffffffffu, sum1, 1);
            sum1 += __shfl_xor_sync(0xffffffffu, sum1, 2);
            l0 = l0 * cr0 + sum0;
            l1 = l1 * cr1 + sum1;
#pragma unroll
            for (int t = 0; t < 8; t++) {
                o[t][0] *= cr0; o[t][1] *= cr0; o[t][2] *= cr1; o[t][3] *= cr1;
            }

#pragma unroll
            for (int ks = 0; ks < 4; ks++) {
                uint32_t ah[4], al[4];
                pack_hilo(s[2*ks][0],   s[2*ks][1],   ah[0], al[0]);
                pack_hilo(s[2*ks][2],   s[2*ks][3],   ah[1], al[1]);
                pack_hilo(s[2*ks+1][0], s[2*ks+1][1], ah[2], al[2]);
                pack_hilo(s[2*ks+1][2], s[2*ks+1][3], ah[3], al[3]);
#pragma unroll
                for (int cp = 0; cp < 4; cp++) {
                    int vrow = ks * 16 + (lane & 15);
                    int vsg = (2 * cp + (lane >> 4)) ^ (vrow & 7);
                    uint32_t va = sstage + 16384 + (uint32_t)(vrow * 64 + vsg * 8) * 2;
                    uint32_t vh0, vh1, vh2, vh3, vl0, vl1, vl2, vl3;
                    ldm_x4_t(vh0, vh1, vh2, vh3, va);
                    ldm_x4_t(vl0, vl1, vl2, vl3, va + 8192);
                    uint32_t bb[2];
                    bb[0] = vh0; bb[1] = vh1;
                    mma16816(o[2*cp],   ah, bb);
                    mma16816(o[2*cp],   al, bb);
                    bb[0] = vl0; bb[1] = vl1;
                    mma16816(o[2*cp],   ah, bb);
                    bb[0] = vh2; bb[1] = vh3;
                    mma16816(o[2*cp+1], ah, bb);
                    mma16816(o[2*cp+1], al, bb);
                    bb[0] = vl2; bb[1] = vl3;
                    mma16816(o[2*cp+1], ah, bb);
                }
            }
        }
        __syncthreads();   // done reading this stage; next iter may overwrite
    }

    const float inv0 = 1.f / l0, inv1 = 1.f / l1;
    const int rg0 = q0 + warp * 16 + (lane >> 2);
    const size_t ro0 = (size_t)(b * SEQ + rg0) * KEXT;
    const size_t ro1 = (size_t)(b * SEQ + rg0 + 8) * KEXT;
#pragma unroll
    for (int nt = 0; nt < 8; nt++) {
        int col = h * DK + nt * 8 + 2 * (lane & 3);
        uint32_t hi, lo;
        pack_hilo(o[nt][0] * inv0, o[nt][1] * inv0, hi, lo);
        *(uint32_t*)(atte + ro0 + col)            = hi;
        *(uint32_t*)(atte + ro0 + DMODEL + col)   = lo;
        *(uint32_t*)(atte + ro0 + 2*DMODEL + col) = hi;
        pack_hilo(o[nt][2] * inv1, o[nt][3] * inv1, hi, lo);
        *(uint32_t*)(atte + ro1 + col)            = hi;
        *(uint32_t*)(atte + ro1 + DMODEL + col)   = lo;
        *(uint32_t*)(atte + ro1 + 2*DMODEL + col) = hi;
    }
}

// ---------------------------------------------------------------------------
// kernel_launch
// ---------------------------------------------------------------------------
extern "C" void kernel_launch(void* const* d_in, const int* in_sizes, int n_in,
                              void* d_out, int out_size)
{
    const float* x     = (const float*)d_in[0];   // [2, 2048, 1024]
    const float* W_qkv = (const float*)d_in[1];   // [3072, 1024]
    const float* W_out = (const float*)d_in[2];   // [1024, 1024]
    float* out = (float*)d_out;                   // [2, 2048, 1024]

    float* qkv_ptr = nullptr;
    __nv_bfloat16 *xe, *wqkve, *wute, *atte;
    cudaGetSymbolAddress((void**)&qkv_ptr, g_qkv);
    cudaGetSymbolAddress((void**)&xe,    g_xe);
    cudaGetSymbolAddress((void**)&wqkve, g_wqkve);
    cudaGetSymbolAddress((void**)&wute,  g_wute);
    cudaGetSymbolAddress((void**)&atte,  g_atte);

    cudaFuncSetAttribute(attn_tc, cudaFuncAttributeMaxDynamicSharedMemorySize, 65536);

    // 0) split conversions (inputs)
    {
        size_t tx_ = (size_t)MTOT * DMODEL;
        conv_split<1><<<(unsigned)((tx_/4 + 255)/256), 256>>>(x, xe, DMODEL, tx_);
        size_t tw = (size_t)QKV_N * DMODEL;
        conv_split<0><<<(unsigned)((tw/4 + 255)/256), 256>>>(W_qkv, wqkve, DMODEL, tw);
        size_t tu = (size_t)DMODEL * DMODEL;
        conv_split<0><<<(unsigned)((tu/4 + 255)/256), 256>>>(W_out, wute, DMODEL, tu);
    }
    // 1) QKV projection: [4096,3072] f32
    {
        dim3 grid(QKV_N / 128, MTOT / 128);
        gemm_bf16<<<grid, 256>>>(xe, wqkve, qkv_ptr, QKV_N);
    }
    // 1b) pre-convert K/V to hi/lo bf16 [b,h,s,dk]
    {
        size_t tot = (size_t)MTOT * DMODEL;
        conv_qkv<<<(unsigned)((tot/4 + 255)/256), 256>>>(qkv_ptr);
    }
    // 2) tensor-core causal flash attention -> g_atte (bf16 split layout)
    {
        dim3 grid(SEQ / 128, NHEADS, BATCH);
        attn_tc<<<grid, 256, 65536>>>(qkv_ptr, atte);
    }
    // 3) output projection -> d_out
    {
        dim3 grid(DMODEL / 128, MTOT / 128);
        gemm_bf16<<<grid, 256>>>(atte, wute, out, DMODEL);
    }
}

// round 8
// speedup vs baseline: 1.1939x; 1.0054x over previous
#include <cuda_runtime.h>
#include <cuda_bf16.h>
#include <math.h>
#include <stdint.h>

// Problem constants
#define BATCH 2
#define SEQ   2048
#define DMODEL 1024
#define NHEADS 16
#define DK    64
#define MTOT  (BATCH*SEQ)          // 4096
#define QKV_N (3*DMODEL)           // 3072
#define KEXT  (3*DMODEL)           // 3072 extended-K for bf16 split

// Scratch (device globals — no allocation allowed)
__device__ float g_qkv[(size_t)MTOT * QKV_N];             // f32 qkv
__device__ __nv_bfloat16 g_xe   [(size_t)MTOT  * KEXT];   // x extended   (A: hi,lo,hi)
__device__ __nv_bfloat16 g_wqkve[(size_t)QKV_N * KEXT];   // W_qkv ext    (B: hi,hi,lo)
__device__ __nv_bfloat16 g_wute [(size_t)DMODEL* KEXT];   // W_out ext    (B)
__device__ __nv_bfloat16 g_atte [(size_t)MTOT  * KEXT];   // attention out ext (A)
// pre-converted K/V, layout [b][h][s][dk] bf16
__device__ __nv_bfloat16 g_khe[(size_t)MTOT * DMODEL];
__device__ __nv_bfloat16 g_kle[(size_t)MTOT * DMODEL];
__device__ __nv_bfloat16 g_vhe[(size_t)MTOT * DMODEL];
__device__ __nv_bfloat16 g_vle[(size_t)MTOT * DMODEL];

// ---------------------------------------------------------------------------
// helpers
// ---------------------------------------------------------------------------
__device__ __forceinline__ void pack_hilo(float a, float b, uint32_t& hi, uint32_t& lo)
{
    __nv_bfloat16 ha = __float2bfloat16_rn(a), hb = __float2bfloat16_rn(b);
    __nv_bfloat162 h; h.x = ha; h.y = hb;
    __nv_bfloat162 l;
    l.x = __float2bfloat16_rn(a - __bfloat162float(ha));
    l.y = __float2bfloat16_rn(b - __bfloat162float(hb));
    hi = *(uint32_t*)&h; lo = *(uint32_t*)&l;
}

__device__ __forceinline__ void ldm_x4(uint32_t& r0, uint32_t& r1, uint32_t& r2, uint32_t& r3,
                                       uint32_t addr)
{
    asm volatile("ldmatrix.sync.aligned.m8n8.x4.shared.b16 {%0,%1,%2,%3}, [%4];"
                 : "=r"(r0), "=r"(r1), "=r"(r2), "=r"(r3) : "r"(addr));
}

__device__ __forceinline__ void ldm_x4_t(uint32_t& r0, uint32_t& r1, uint32_t& r2, uint32_t& r3,
                                         uint32_t addr)
{
    asm volatile("ldmatrix.sync.aligned.m8n8.x4.trans.shared.b16 {%0,%1,%2,%3}, [%4];"
                 : "=r"(r0), "=r"(r1), "=r"(r2), "=r"(r3) : "r"(addr));
}

__device__ __forceinline__ void mma16816(float* d, const uint32_t* a, const uint32_t* b)
{
    asm volatile(
        "mma.sync.aligned.m16n8k16.row.col.f32.bf16.bf16.f32 "
        "{%0,%1,%2,%3}, {%4,%5,%6,%7}, {%8,%9}, {%0,%1,%2,%3};"
        : "+f"(d[0]), "+f"(d[1]), "+f"(d[2]), "+f"(d[3])
        : "r"(a[0]), "r"(a[1]), "r"(a[2]), "r"(a[3]), "r"(b[0]), "r"(b[1]));
}

__device__ __forceinline__ void cp16(uint32_t saddr, const void* gptr)
{
    asm volatile("cp.async.cg.shared.global [%0], [%1], 16;" :: "r"(saddr), "l"(gptr));
}

__device__ __forceinline__ void cvt_store8(__nv_bfloat16* dhi, __nv_bfloat16* dlo,
                                           float4 f0, float4 f1)
{
    uint32_t h0,h1,h2,h3,l0,l1,l2,l3;
    pack_hilo(f0.x, f0.y, h0, l0);
    pack_hilo(f0.z, f0.w, h1, l1);
    pack_hilo(f1.x, f1.y, h2, l2);
    pack_hilo(f1.z, f1.w, h3, l3);
    *(uint4*)dhi = make_uint4(h0, h1, h2, h3);
    *(uint4*)dlo = make_uint4(l0, l1, l2, l3);
}

// ---------------------------------------------------------------------------
// Split-conversion kernels: f32 [R,K] -> bf16 [R,3K]
// ---------------------------------------------------------------------------
template<int ISA>
__global__ void conv_split(const float* __restrict__ in, __nv_bfloat16* __restrict__ out,
                           int K, size_t total)
{
    size_t idx = ((size_t)blockIdx.x * blockDim.x + threadIdx.x) * 4;
    if (idx >= total) return;
    int r = (int)(idx / K);
    int k = (int)(idx % K);
    float4 v = *(const float4*)(in + idx);
    uint32_t hi01, hi23, lo01, lo23;
    pack_hilo(v.x, v.y, hi01, lo01);
    pack_hilo(v.z, v.w, hi23, lo23);
    __nv_bfloat16* o = out + (size_t)r * (3 * K) + k;
    *(uint32_t*)(o + 0) = hi01;  *(uint32_t*)(o + 2) = hi23;
    if (ISA) {
        *(uint32_t*)(o + K + 0)     = lo01; *(uint32_t*)(o + K + 2)     = lo23;
        *(uint32_t*)(o + 2 * K + 0) = hi01; *(uint32_t*)(o + 2 * K + 2) = hi23;
    } else {
        *(uint32_t*)(o + K + 0)     = hi01; *(uint32_t*)(o + K + 2)     = hi23;
        *(uint32_t*)(o + 2 * K + 0) = lo01; *(uint32_t*)(o + 2 * K + 2) = lo23;
    }
}

// ---------------------------------------------------------------------------
// conv_qkv: pre-convert K and V slabs of g_qkv to hi/lo bf16, [b,h,s,dk].
// ---------------------------------------------------------------------------
__global__ void conv_qkv(const float* __restrict__ qkv)
{
    size_t idx = ((size_t)blockIdx.x * blockDim.x + threadIdx.x) * 4;   // over MTOT*DMODEL
    if (idx >= (size_t)MTOT * DMODEL) return;
    int r = (int)(idx >> 10);          // row in [0,4096)
    int c = (int)(idx & 1023);         // col in [0,1024)
    int h = c >> 6, d = c & 63;
    int b = r >> 11, s = r & 2047;
    size_t dst = (((size_t)(b * NHEADS + h)) * SEQ + s) * DK + d;

    const float* src = qkv + (size_t)r * QKV_N + DMODEL + c;
    float4 kv = *(const float4*)src;
    float4 vv = *(const float4*)(src + DMODEL);
    uint32_t h01, h23, l01, l23;
    pack_hilo(kv.x, kv.y, h01, l01); pack_hilo(kv.z, kv.w, h23, l23);
    *(uint32_t*)&g_khe[dst] = h01; *(uint32_t*)&g_khe[dst + 2] = h23;
    *(uint32_t*)&g_kle[dst] = l01; *(uint32_t*)&g_kle[dst + 2] = l23;
    pack_hilo(vv.x, vv.y, h01, l01); pack_hilo(vv.z, vv.w, h23, l23);
    *(uint32_t*)&g_vhe[dst] = h01; *(uint32_t*)&g_vhe[dst + 2] = h23;
    *(uint32_t*)&g_vle[dst] = l01; *(uint32_t*)&g_vle[dst + 2] = l23;
}

// ---------------------------------------------------------------------------
// bf16 tensor-core GEMM: 128x128 block, BK=32, 256 thr, warp tile 64x32.
// 4-stage cp.async ring, ONE __syncthreads per K-step.
// Stage s: A @ s*16KB (8KB), B @ s*16KB+8KB (8KB). Dynamic smem = 64KB.
// ---------------------------------------------------------------------------
#define GSTAGE_BYTES 16384

__global__ void __launch_bounds__(256, 2) gemm_bf16(
    const __nv_bfloat16* __restrict__ A, const __nv_bfloat16* __restrict__ B,
    float* __restrict__ C, int N)
{
    extern __shared__ __nv_bfloat16 gsm[];
    const uint32_t sbase = (uint32_t)__cvta_generic_to_shared(gsm);

    const int tid  = threadIdx.x;
    const int lane = tid & 31;
    const int warp = tid >> 5;
    const int wr = warp >> 2;
    const int wc = warp & 3;
    const int mBase = blockIdx.y * 128;
    const int nBase = blockIdx.x * 128;

    // load mapping: rows {lrow, lrow+64}, seg lseg (16B)
    const int lrow = tid >> 2;
    const int lseg = tid & 3;
    const uint32_t swz0 = (uint32_t)(lrow * 32 + ((lseg ^ ((lrow >> 1) & 3)) * 8)) * 2;
    const uint32_t swz1 = (uint32_t)((lrow + 64) * 32 + ((lseg ^ (((lrow + 64) >> 1) & 3)) * 8)) * 2;
    const __nv_bfloat16* gA0 = A + (size_t)(mBase + lrow)      * KEXT + lseg * 8;
    const __nv_bfloat16* gA1 = A + (size_t)(mBase + lrow + 64) * KEXT + lseg * 8;
    const __nv_bfloat16* gB0 = B + (size_t)(nBase + lrow)      * KEXT + lseg * 8;
    const __nv_bfloat16* gB1 = B + (size_t)(nBase + lrow + 64) * KEXT + lseg * 8;

    const int arow = wr * 64 + (lane & 15);
    const int aseg = (lane >> 4) & 1;
    const int brow = wc * 32 + (lane & 7) + (((lane >> 4) & 1) << 3);
    const int bseg = (lane >> 3) & 1;

    float acc[4][4][4];
#pragma unroll
    for (int a = 0; a < 4; a++)
#pragma unroll
        for (int n = 0; n < 4; n++)
#pragma unroll
            for (int i = 0; i < 4; i++) acc[a][n][i] = 0.f;

    const int NTILES = KEXT / 32;     // 96 (divisible by 4)

    // prologue: stages 0,1,2
#pragma unroll
    for (int s = 0; s < 3; s++) {
        const uint32_t st = sbase + s * GSTAGE_BYTES;
        const int k0 = s * 32;
        cp16(st + swz0, gA0 + k0);         cp16(st + swz1, gA1 + k0);
        cp16(st + 8192 + swz0, gB0 + k0);  cp16(st + 8192 + swz1, gB1 + k0);
        asm volatile("cp.async.commit_group;");
    }

    for (int t = 0; t < NTILES; t++) {
        // wait for stage t (allow pending = #stages issued beyond t)
        if (t < NTILES - 2)       asm volatile("cp.async.wait_group 2;");
        else if (t == NTILES - 2) asm volatile("cp.async.wait_group 1;");
        else                      asm volatile("cp.async.wait_group 0;");
        __syncthreads();

        // issue stage t+3 (buffer (t+3)&3 was last read at iter t-1, safe after barrier)
        if (t + 3 < NTILES) {
            const uint32_t st = sbase + ((t + 3) & 3) * GSTAGE_BYTES;
            const int k0 = (t + 3) * 32;
            cp16(st + swz0, gA0 + k0);         cp16(st + swz1, gA1 + k0);
            cp16(st + 8192 + swz0, gB0 + k0);  cp16(st + 8192 + swz1, gB1 + k0);
            asm volatile("cp.async.commit_group;");
        }

        const uint32_t aBase = sbase + (t & 3) * GSTAGE_BYTES;
        const uint32_t bBase = aBase + 8192;

#pragma unroll
        for (int kk = 0; kk < 2; kk++) {
            uint32_t af[4][4];
#pragma unroll
            for (int a = 0; a < 4; a++) {
                int r = arow + a * 16;
                int seg = (kk * 2 + aseg) ^ ((r >> 1) & 3);
                ldm_x4(af[a][0], af[a][1], af[a][2], af[a][3],
                       aBase + (uint32_t)(r * 32 + seg * 8) * 2);
            }
            uint32_t bf[4][2];
#pragma unroll
            for (int p = 0; p < 2; p++) {
                int n = brow + p * 16;
                int seg = (kk * 2 + bseg) ^ ((n >> 1) & 3);
                uint32_t r0, r1, r2, r3;
                ldm_x4(r0, r1, r2, r3, bBase + (uint32_t)(n * 32 + seg * 8) * 2);
                bf[p * 2 + 0][0] = r0; bf[p * 2 + 0][1] = r1;
                bf[p * 2 + 1][0] = r2; bf[p * 2 + 1][1] = r3;
            }
#pragma unroll
            for (int a = 0; a < 4; a++)
#pragma unroll
                for (int n = 0; n < 4; n++)
                    mma16816(acc[a][n], af[a], bf[n]);
        }
    }

#pragma unroll
    for (int a = 0; a < 4; a++) {
        int row0 = mBase + wr * 64 + a * 16 + (lane >> 2);
#pragma unroll
        for (int n = 0; n < 4; n++) {
            int col = nBase + wc * 32 + n * 8 + (lane & 3) * 2;
            *(float2*)&C[(size_t)row0 * N + col]       = make_float2(acc[a][n][0], acc[a][n][1]);
            *(float2*)&C[(size_t)(row0 + 8) * N + col] = make_float2(acc[a][n][2], acc[a][n][3]);
        }
    }
}

// ---------------------------------------------------------------------------
// Tensor-core causal flash attention, bf16 hi/lo split, cp.async K/V pipeline.
// (unchanged from R7)
// ---------------------------------------------------------------------------
__global__ void __launch_bounds__(256, 1) attn_tc(
    const float* __restrict__ qkv, __nv_bfloat16* __restrict__ atte)
{
    extern __shared__ __nv_bfloat16 sm[];
    const uint32_t sbase = (uint32_t)__cvta_generic_to_shared(sm);

    const int b = blockIdx.z, h = blockIdx.y;
    const int qt = (int)(gridDim.x - 1 - blockIdx.x);   // heavy tiles first
    const int q0 = qt * 128;
    const int tid = threadIdx.x;
    const int lane = tid & 31, warp = tid >> 5;

    const size_t kvbase = ((size_t)(b * NHEADS + h)) * SEQ * DK;
    const __nv_bfloat16* mats[4] = { g_khe + kvbase, g_kle + kvbase,
                                     g_vhe + kvbase, g_vle + kvbase };

    uint32_t dstoff[8];
    const __nv_bfloat16* srcp[8];
#pragma unroll
    for (int j = 0; j < 8; j++) {
        int c = tid + j * 256;
        int m = c >> 9;
        int w = c & 511;
        int r = w >> 3, sg = w & 7;
        dstoff[j] = (uint32_t)(m * 8192) + (uint32_t)(r * 64 + ((sg ^ (r & 7)) * 8)) * 2;
        srcp[j] = mats[m] + r * DK + sg * 8;
    }

    for (int e = tid; e < 1024; e += 256) {
        int r = e >> 3, sg = e & 7;
        const float* gq = qkv + ((size_t)(b * SEQ + q0 + r)) * QKV_N + h * DK + sg * 8;
        float4 f0 = *(const float4*)gq;
        float4 f1 = *(const float4*)(gq + 4);
        f0.x *= 0.125f; f0.y *= 0.125f; f0.z *= 0.125f; f0.w *= 0.125f;
        f1.x *= 0.125f; f1.y *= 0.125f; f1.z *= 0.125f; f1.w *= 0.125f;
        int off = r * 64 + ((sg ^ (r & 7)) * 8);
        cvt_store8(sm + off, sm + 8192 + off, f0, f1);
    }
    __syncthreads();

#pragma unroll
    for (int j = 0; j < 8; j++) cp16(sbase + 32768 + dstoff[j], srcp[j]);
    asm volatile("cp.async.commit_group;");

    uint32_t qh[4][4], ql[4][4];
    {
        const int r = warp * 16 + (lane & 15);
        const int sgx = lane >> 4;
#pragma unroll
        for (int ks = 0; ks < 4; ks++) {
            int sg = (2 * ks + sgx) ^ (r & 7);
            uint32_t ad = sbase + (uint32_t)(r * 64 + sg * 8) * 2;
            ldm_x4(qh[ks][0], qh[ks][1], qh[ks][2], qh[ks][3], ad);
            ldm_x4(ql[ks][0], ql[ks][1], ql[ks][2], ql[ks][3], ad + 16384);
        }
    }
    __syncthreads();

    float o[8][4];
#pragma unroll
    for (int t = 0; t < 8; t++) { o[t][0]=0.f; o[t][1]=0.f; o[t][2]=0.f; o[t][3]=0.f; }
    float m0 = -1e30f, m1 = -1e30f, l0 = 0.f, l1 = 0.f;

    const int ktmax = q0 / 64 + 1;
    for (int kt = 0; kt <= ktmax; kt++) {
        const int kbase = kt * 64;
        if (kt + 1 <= ktmax) {
            const uint32_t so = (uint32_t)(kt & 1) * 32768;
            const size_t goff = (size_t)(kbase + 64) * DK;
#pragma unroll
            for (int j = 0; j < 8; j++) cp16(sbase + so + dstoff[j], srcp[j] + goff);
            asm volatile("cp.async.commit_group;");
            asm volatile("cp.async.wait_group 1;");
        } else {
            asm volatile("cp.async.wait_group 0;");
        }
        __syncthreads();
        const uint32_t sstage = sbase + (uint32_t)((kt + 1) & 1) * 32768;

        if (kbase <= q0 + warp * 16 + 15) {
            float s[8][4];
#pragma unroll
            for (int t = 0; t < 8; t++) { s[t][0]=0.f; s[t][1]=0.f; s[t][2]=0.f; s[t][3]=0.f; }

#pragma unroll
            for (int kk = 0; kk < 4; kk++) {
#pragma unroll
                for (int np = 0; np < 4; np++) {
                    int krow = np * 16 + (lane & 7) + (((lane >> 4) & 1) << 3);
                    int ksg = (2 * kk + ((lane >> 3) & 1)) ^ (krow & 7);
                    uint32_t ad = sstage + (uint32_t)(krow * 64 + ksg * 8) * 2;
                    uint32_t bh0, bh1, bh2, bh3, bl0, bl1, bl2, bl3;
                    ldm_x4(bh0, bh1, bh2, bh3, ad);
                    ldm_x4(bl0, bl1, bl2, bl3, ad + 8192);
                    uint32_t bb[2];
                    bb[0] = bh0; bb[1] = bh1;
                    mma16816(s[2*np],   qh[kk], bb);
                    mma16816(s[2*np],   ql[kk], bb);
                    bb[0] = bh2; bb[1] = bh3;
                    mma16816(s[2*np+1], qh[kk], bb);
                    mma16816(s[2*np+1], ql[kk], bb);
                    bb[0] = bl0; bb[1] = bl1;
                    mma16816(s[2*np],   qh[kk], bb);
                    bb[0] = bl2; bb[1] = bl3;
                    mma16816(s[2*np+1], qh[kk], bb);
                }
            }

            const int rg0 = q0 + warp * 16 + (lane >> 2);
            if (kbase + 63 > q0 + warp * 16) {
#pragma unroll
                for (int nt = 0; nt < 8; nt++) {
                    int c0 = kbase + nt * 8 + 2 * (lane & 3);
                    if (c0     > rg0)     s[nt][0] = -1e30f;
                    if (c0 + 1 > rg0)     s[nt][1] = -1e30f;
                    if (c0     > rg0 + 8) s[nt][2] = -1e30f;
                    if (c0 + 1 > rg0 + 8) s[nt][3] = -1e30f;
                }
            }

            float mx0 = -1e30f, mx1 = -1e30f;
#pragma unroll
            for (int nt = 0; nt < 8; nt++) {
                mx0 = fmaxf(mx0, fmaxf(s[nt][0], s[nt][1]));
                mx1 = fmaxf(mx1, fmaxf(s[nt][2], s[nt][3]));
            }
            mx0 = fmaxf(mx0, __shfl_xor_sync(0xffffffffu, mx0, 1));
            mx0 = fmaxf(mx0, __shfl_xor_sync(0xffffffffu, mx0, 2));
            mx1 = fmaxf(mx1, __shfl_xor_sync(0xffffffffu, mx1, 1));
            mx1 = fmaxf(mx1, __shfl_xor_sync(0xffffffffu, mx1, 2));
            float mn0 = fmaxf(m0, mx0), mn1 = fmaxf(m1, mx1);
            float cr0 = __expf(m0 - mn0), cr1 = __expf(m1 - mn1);
            m0 = mn0; m1 = mn1;
            float sum0 = 0.f, sum1 = 0.f;
#pragma unroll
            for (int nt = 0; nt < 8; nt++) {
                s[nt][0] = __expf(s[nt][0] - mn0);
                s[nt][1] = __expf(s[nt][1] - mn0);
                s[nt][2] = __expf(s[nt][2] - mn1);
                s[nt][3] = __expf(s[nt][3] - mn1);
                sum0 += s[nt][0] + s[nt][1];
                sum1 += s[nt][2] + s[nt][3];
            }
            sum0 += __shfl_xor_sync(0xffffffffu, sum0, 1);
            sum0 += __shfl_xor_sync(0xffffffffu, sum0, 2);
            sum1 += __shfl_xor_sync(0xffffffffu, sum1, 1);
            sum1 += __shfl_xor_sync(0xffffffffu, sum1, 2);
            l0 = l0 * cr0 + sum0;
            l1 = l1 * cr1 + sum1;
#pragma unroll
            for (int t = 0; t < 8; t++) {
                o[t][0] *= cr0; o[t][1] *= cr0; o[t][2] *= cr1; o[t][3] *= cr1;
            }

#pragma unroll
            for (int ks = 0; ks < 4; ks++) {
                uint32_t ah[4], al[4];
                pack_hilo(s[2*ks][0],   s[2*ks][1],   ah[0], al[0]);
                pack_hilo(s[2*ks][2],   s[2*ks][3],   ah[1], al[1]);
                pack_hilo(s[2*ks+1][0], s[2*ks+1][1], ah[2], al[2]);
                pack_hilo(s[2*ks+1][2], s[2*ks+1][3], ah[3], al[3]);
#pragma unroll
                for (int cp = 0; cp < 4; cp++) {
                    int vrow = ks * 16 + (lane & 15);
                    int vsg = (2 * cp + (lane >> 4)) ^ (vrow & 7);
                    uint32_t va = sstage + 16384 + (uint32_t)(vrow * 64 + vsg * 8) * 2;
                    uint32_t vh0, vh1, vh2, vh3, vl0, vl1, vl2, vl3;
                    ldm_x4_t(vh0, vh1, vh2, vh3, va);
                    ldm_x4_t(vl0, vl1, vl2, vl3, va + 8192);
                    uint32_t bb[2];
                    bb[0] = vh0; bb[1] = vh1;
                    mma16816(o[2*cp],   ah, bb);
                    mma16816(o[2*cp],   al, bb);
                    bb[0] = vl0; bb[1] = vl1;
                    mma16816(o[2*cp],   ah, bb);
                    bb[0] = vh2; bb[1] = vh3;
                    mma16816(o[2*cp+1], ah, bb);
                    mma16816(o[2*cp+1], al, bb);
                    bb[0] = vl2; bb[1] = vl3;
                    mma16816(o[2*cp+1], ah, bb);
                }
            }
        }
        __syncthreads();
    }

    const float inv0 = 1.f / l0, inv1 = 1.f / l1;
    const int rg0 = q0 + warp * 16 + (lane >> 2);
    const size_t ro0 = (size_t)(b * SEQ + rg0) * KEXT;
    const size_t ro1 = (size_t)(b * SEQ + rg0 + 8) * KEXT;
#pragma unroll
    for (int nt = 0; nt < 8; nt++) {
        int col = h * DK + nt * 8 + 2 * (lane & 3);
        uint32_t hi, lo;
        pack_hilo(o[nt][0] * inv0, o[nt][1] * inv0, hi, lo);
        *(uint32_t*)(atte + ro0 + col)            = hi;
        *(uint32_t*)(atte + ro0 + DMODEL + col)   = lo;
        *(uint32_t*)(atte + ro0 + 2*DMODEL + col) = hi;
        pack_hilo(o[nt][2] * inv1, o[nt][3] * inv1, hi, lo);
        *(uint32_t*)(atte + ro1 + col)            = hi;
        *(uint32_t*)(atte + ro1 + DMODEL + col)   = lo;
        *(uint32_t*)(atte + ro1 + 2*DMODEL + col) = hi;
    }
}

// ---------------------------------------------------------------------------
// kernel_launch
// ---------------------------------------------------------------------------
extern "C" void kernel_launch(void* const* d_in, const int* in_sizes, int n_in,
                              void* d_out, int out_size)
{
    const float* x     = (const float*)d_in[0];   // [2, 2048, 1024]
    const float* W_qkv = (const float*)d_in[1];   // [3072, 1024]
    const float* W_out = (const float*)d_in[2];   // [1024, 1024]
    float* out = (float*)d_out;                   // [2, 2048, 1024]

    float* qkv_ptr = nullptr;
    __nv_bfloat16 *xe, *wqkve, *wute, *atte;
    cudaGetSymbolAddress((void**)&qkv_ptr, g_qkv);
    cudaGetSymbolAddress((void**)&xe,    g_xe);
    cudaGetSymbolAddress((void**)&wqkve, g_wqkve);
    cudaGetSymbolAddress((void**)&wute,  g_wute);
    cudaGetSymbolAddress((void**)&atte,  g_atte);

    cudaFuncSetAttribute(gemm_bf16, cudaFuncAttributeMaxDynamicSharedMemorySize, 65536);
    cudaFuncSetAttribute(attn_tc,   cudaFuncAttributeMaxDynamicSharedMemorySize, 65536);

    // 0) split conversions (inputs)
    {
        size_t tx_ = (size_t)MTOT * DMODEL;
        conv_split<1><<<(unsigned)((tx_/4 + 255)/256), 256>>>(x, xe, DMODEL, tx_);
        size_t tw = (size_t)QKV_N * DMODEL;
        conv_split<0><<<(unsigned)((tw/4 + 255)/256), 256>>>(W_qkv, wqkve, DMODEL, tw);
        size_t tu = (size_t)DMODEL * DMODEL;
        conv_split<0><<<(unsigned)((tu/4 + 255)/256), 256>>>(W_out, wute, DMODEL, tu);
    }
    // 1) QKV projection: [4096,3072] f32
    {
        dim3 grid(QKV_N / 128, MTOT / 128);
        gemm_bf16<<<grid, 256, 65536>>>(xe, wqkve, qkv_ptr, QKV_N);
    }
    // 1b) pre-convert K/V to hi/lo bf16 [b,h,s,dk]
    {
        size_t tot = (size_t)MTOT * DMODEL;
        conv_qkv<<<(unsigned)((tot/4 + 255)/256), 256>>>(qkv_ptr);
    }
    // 2) tensor-core causal flash attention -> g_atte (bf16 split layout)
    {
        dim3 grid(SEQ / 128, NHEADS, BATCH);
        attn_tc<<<grid, 256, 65536>>>(qkv_ptr, atte);
    }
    // 3) output projection -> d_out
    {
        dim3 grid(DMODEL / 128, MTOT / 128);
        gemm_bf16<<<grid, 256, 65536>>>(atte, wute, out, DMODEL);
    }
}

// round 9
// speedup vs baseline: 1.2071x; 1.0111x over previous
#include <cuda_runtime.h>
#include <cuda_bf16.h>
#include <math.h>
#include <stdint.h>

// Problem constants
#define BATCH 2
#define SEQ   2048
#define DMODEL 1024
#define NHEADS 16
#define DK    64
#define MTOT  (BATCH*SEQ)          // 4096
#define QKV_N (3*DMODEL)           // 3072
#define KEXT  (3*DMODEL)           // 3072 extended-K for bf16 split
#define KV_MS ((size_t)MTOT * DMODEL)   // per-matrix stride in g_kv

// Scratch (device globals — no allocation allowed)
__device__ float g_qkv[(size_t)MTOT * QKV_N];             // f32 qkv
__device__ __nv_bfloat16 g_xe   [(size_t)MTOT  * KEXT];   // x extended   (A: hi,lo,hi)
__device__ __nv_bfloat16 g_wqkve[(size_t)QKV_N * KEXT];   // W_qkv ext    (B: hi,hi,lo)
__device__ __nv_bfloat16 g_wute [(size_t)DMODEL* KEXT];   // W_out ext    (B)
__device__ __nv_bfloat16 g_atte [(size_t)MTOT  * KEXT];   // attention out ext (A)
// pre-converted K/V: [m][b*h][s][dk], m = {Khi, Klo, Vhi, Vlo}
__device__ __nv_bfloat16 g_kv[(size_t)4 * MTOT * DMODEL];

// ---------------------------------------------------------------------------
// helpers
// ---------------------------------------------------------------------------
__device__ __forceinline__ void pack_hilo(float a, float b, uint32_t& hi, uint32_t& lo)
{
    __nv_bfloat16 ha = __float2bfloat16_rn(a), hb = __float2bfloat16_rn(b);
    __nv_bfloat162 h; h.x = ha; h.y = hb;
    __nv_bfloat162 l;
    l.x = __float2bfloat16_rn(a - __bfloat162float(ha));
    l.y = __float2bfloat16_rn(b - __bfloat162float(hb));
    hi = *(uint32_t*)&h; lo = *(uint32_t*)&l;
}

__device__ __forceinline__ void ldm_x4(uint32_t& r0, uint32_t& r1, uint32_t& r2, uint32_t& r3,
                                       uint32_t addr)
{
    asm volatile("ldmatrix.sync.aligned.m8n8.x4.shared.b16 {%0,%1,%2,%3}, [%4];"
                 : "=r"(r0), "=r"(r1), "=r"(r2), "=r"(r3) : "r"(addr));
}

__device__ __forceinline__ void ldm_x4_t(uint32_t& r0, uint32_t& r1, uint32_t& r2, uint32_t& r3,
                                         uint32_t addr)
{
    asm volatile("ldmatrix.sync.aligned.m8n8.x4.trans.shared.b16 {%0,%1,%2,%3}, [%4];"
                 : "=r"(r0), "=r"(r1), "=r"(r2), "=r"(r3) : "r"(addr));
}

__device__ __forceinline__ void mma16816(float* d, const uint32_t* a, const uint32_t* b)
{
    asm volatile(
        "mma.sync.aligned.m16n8k16.row.col.f32.bf16.bf16.f32 "
        "{%0,%1,%2,%3}, {%4,%5,%6,%7}, {%8,%9}, {%0,%1,%2,%3};"
        : "+f"(d[0]), "+f"(d[1]), "+f"(d[2]), "+f"(d[3])
        : "r"(a[0]), "r"(a[1]), "r"(a[2]), "r"(a[3]), "r"(b[0]), "r"(b[1]));
}

__device__ __forceinline__ void cp16(uint32_t saddr, const void* gptr)
{
    asm volatile("cp.async.cg.shared.global [%0], [%1], 16;" :: "r"(saddr), "l"(gptr));
}

__device__ __forceinline__ void cvt_store8(__nv_bfloat16* dhi, __nv_bfloat16* dlo,
                                           float4 f0, float4 f1)
{
    uint32_t h0,h1,h2,h3,l0,l1,l2,l3;
    pack_hilo(f0.x, f0.y, h0, l0);
    pack_hilo(f0.z, f0.w, h1, l1);
    pack_hilo(f1.x, f1.y, h2, l2);
    pack_hilo(f1.z, f1.w, h3, l3);
    *(uint4*)dhi = make_uint4(h0, h1, h2, h3);
    *(uint4*)dlo = make_uint4(l0, l1, l2, l3);
}

// ---------------------------------------------------------------------------
// Split-conversion kernels: f32 [R,K] -> bf16 [R,3K]
// ---------------------------------------------------------------------------
template<int ISA>
__global__ void conv_split(const float* __restrict__ in, __nv_bfloat16* __restrict__ out,
                           int K, size_t total)
{
    size_t idx = ((size_t)blockIdx.x * blockDim.x + threadIdx.x) * 4;
    if (idx >= total) return;
    int r = (int)(idx / K);
    int k = (int)(idx % K);
    float4 v = *(const float4*)(in + idx);
    uint32_t hi01, hi23, lo01, lo23;
    pack_hilo(v.x, v.y, hi01, lo01);
    pack_hilo(v.z, v.w, hi23, lo23);
    __nv_bfloat16* o = out + (size_t)r * (3 * K) + k;
    *(uint32_t*)(o + 0) = hi01;  *(uint32_t*)(o + 2) = hi23;
    if (ISA) {
        *(uint32_t*)(o + K + 0)     = lo01; *(uint32_t*)(o + K + 2)     = lo23;
        *(uint32_t*)(o + 2 * K + 0) = hi01; *(uint32_t*)(o + 2 * K + 2) = hi23;
    } else {
        *(uint32_t*)(o + K + 0)     = hi01; *(uint32_t*)(o + K + 2)     = hi23;
        *(uint32_t*)(o + 2 * K + 0) = lo01; *(uint32_t*)(o + 2 * K + 2) = lo23;
    }
}

// ---------------------------------------------------------------------------
// conv_qkv: pre-convert K and V slabs of g_qkv to hi/lo bf16 into g_kv.
// ---------------------------------------------------------------------------
__global__ void conv_qkv(const float* __restrict__ qkv)
{
    size_t idx = ((size_t)blockIdx.x * blockDim.x + threadIdx.x) * 4;   // over MTOT*DMODEL
    if (idx >= (size_t)MTOT * DMODEL) return;
    int r = (int)(idx >> 10);          // row in [0,4096)
    int c = (int)(idx & 1023);         // col in [0,1024)
    int h = c >> 6, d = c & 63;
    int b = r >> 11, s = r & 2047;
    size_t off = (((size_t)(b * NHEADS + h)) * SEQ + s) * DK + d;

    const float* src = qkv + (size_t)r * QKV_N + DMODEL + c;
    float4 kv = *(const float4*)src;
    float4 vv = *(const float4*)(src + DMODEL);
    uint32_t h01, h23, l01, l23;
    pack_hilo(kv.x, kv.y, h01, l01); pack_hilo(kv.z, kv.w, h23, l23);
    *(uint32_t*)&g_kv[0 * KV_MS + off] = h01; *(uint32_t*)&g_kv[0 * KV_MS + off + 2] = h23;
    *(uint32_t*)&g_kv[1 * KV_MS + off] = l01; *(uint32_t*)&g_kv[1 * KV_MS + off + 2] = l23;
    pack_hilo(vv.x, vv.y, h01, l01); pack_hilo(vv.z, vv.w, h23, l23);
    *(uint32_t*)&g_kv[2 * KV_MS + off] = h01; *(uint32_t*)&g_kv[2 * KV_MS + off + 2] = h23;
    *(uint32_t*)&g_kv[3 * KV_MS + off] = l01; *(uint32_t*)&g_kv[3 * KV_MS + off + 2] = l23;
}

// ---------------------------------------------------------------------------
// bf16 tensor-core GEMM: 128x128 block, BK=64, 256 thr, warp tile 64x32.
// 3-stage cp.async ring (32KB/stage), ONE __syncthreads per 64-K step.
// Stage layout: [A_k0 8KB][A_k1 8KB][B_k0 8KB][B_k1 8KB].
// ---------------------------------------------------------------------------
#define GSTAGE_BYTES 32768

__global__ void __launch_bounds__(256, 2) gemm_bf16(
    const __nv_bfloat16* __restrict__ A, const __nv_bfloat16* __restrict__ B,
    float* __restrict__ C, int N)
{
    extern __shared__ __nv_bfloat16 gsm[];
    const uint32_t sbase = (uint32_t)__cvta_generic_to_shared(gsm);

    const int tid  = threadIdx.x;
    const int lane = tid & 31;
    const int warp = tid >> 5;
    const int wr = warp >> 2;
    const int wc = warp & 3;
    const int mBase = blockIdx.y * 128;
    const int nBase = blockIdx.x * 128;

    const int lrow = tid >> 2;
    const int lseg = tid & 3;
    const uint32_t swz0 = (uint32_t)(lrow * 32 + ((lseg ^ ((lrow >> 1) & 3)) * 8)) * 2;
    const uint32_t swz1 = (uint32_t)((lrow + 64) * 32 + ((lseg ^ (((lrow + 64) >> 1) & 3)) * 8)) * 2;
    const __nv_bfloat16* gA0 = A + (size_t)(mBase + lrow)      * KEXT + lseg * 8;
    const __nv_bfloat16* gA1 = A + (size_t)(mBase + lrow + 64) * KEXT + lseg * 8;
    const __nv_bfloat16* gB0 = B + (size_t)(nBase + lrow)      * KEXT + lseg * 8;
    const __nv_bfloat16* gB1 = B + (size_t)(nBase + lrow + 64) * KEXT + lseg * 8;

    const int arow = wr * 64 + (lane & 15);
    const int aseg = (lane >> 4) & 1;
    const int brow = wc * 32 + (lane & 7) + (((lane >> 4) & 1) << 3);
    const int bseg = (lane >> 3) & 1;

    float acc[4][4][4];
#pragma unroll
    for (int a = 0; a < 4; a++)
#pragma unroll
        for (int n = 0; n < 4; n++)
#pragma unroll
            for (int i = 0; i < 4; i++) acc[a][n][i] = 0.f;

    const int NSTEP = KEXT / 64;     // 48

    // prologue: stages 0,1
#pragma unroll
    for (int s = 0; s < 2; s++) {
        const uint32_t st = sbase + s * GSTAGE_BYTES;
        const int k0 = s * 64;
#pragma unroll
        for (int hf = 0; hf < 2; hf++) {
            cp16(st + hf * 8192 + swz0,          gA0 + k0 + hf * 32);
            cp16(st + hf * 8192 + swz1,          gA1 + k0 + hf * 32);
            cp16(st + 16384 + hf * 8192 + swz0,  gB0 + k0 + hf * 32);
            cp16(st + 16384 + hf * 8192 + swz1,  gB1 + k0 + hf * 32);
        }
        asm volatile("cp.async.commit_group;");
    }

    int cur = 0, nxt = 2;
    for (int t = 0; t < NSTEP; t++) {
        if (t + 1 < NSTEP) asm volatile("cp.async.wait_group 1;");
        else               asm volatile("cp.async.wait_group 0;");
        __syncthreads();

        if (t + 2 < NSTEP) {
            const uint32_t st = sbase + nxt * GSTAGE_BYTES;
            const int k0 = (t + 2) * 64;
#pragma unroll
            for (int hf = 0; hf < 2; hf++) {
                cp16(st + hf * 8192 + swz0,          gA0 + k0 + hf * 32);
                cp16(st + hf * 8192 + swz1,          gA1 + k0 + hf * 32);
                cp16(st + 16384 + hf * 8192 + swz0,  gB0 + k0 + hf * 32);
                cp16(st + 16384 + hf * 8192 + swz1,  gB1 + k0 + hf * 32);
            }
            asm volatile("cp.async.commit_group;");
        }

#pragma unroll
        for (int hf = 0; hf < 2; hf++) {
            const uint32_t aBase = sbase + cur * GSTAGE_BYTES + hf * 8192;
            const uint32_t bBase = aBase + 16384;

#pragma unroll
            for (int kk = 0; kk < 2; kk++) {
                uint32_t af[4][4];
#pragma unroll
                for (int a = 0; a < 4; a++) {
                    int r = arow + a * 16;
                    int seg = (kk * 2 + aseg) ^ ((r >> 1) & 3);
                    ldm_x4(af[a][0], af[a][1], af[a][2], af[a][3],
                           aBase + (uint32_t)(r * 32 + seg * 8) * 2);
                }
                uint32_t bf[4][2];
#pragma unroll
                for (int p = 0; p < 2; p++) {
                    int n = brow + p * 16;
                    int seg = (kk * 2 + bseg) ^ ((n >> 1) & 3);
                    uint32_t r0, r1, r2, r3;
                    ldm_x4(r0, r1, r2, r3, bBase + (uint32_t)(n * 32 + seg * 8) * 2);
                    bf[p * 2 + 0][0] = r0; bf[p * 2 + 0][1] = r1;
                    bf[p * 2 + 1][0] = r2; bf[p * 2 + 1][1] = r3;
                }
#pragma unroll
                for (int a = 0; a < 4; a++)
#pragma unroll
                    for (int n = 0; n < 4; n++)
                        mma16816(acc[a][n], af[a], bf[n]);
            }
        }
        cur = (cur == 2) ? 0 : cur + 1;
        nxt = (nxt == 2) ? 0 : nxt + 1;
    }

#pragma unroll
    for (int a = 0; a < 4; a++) {
        int row0 = mBase + wr * 64 + a * 16 + (lane >> 2);
#pragma unroll
        for (int n = 0; n < 4; n++) {
            int col = nBase + wc * 32 + n * 8 + (lane & 3) * 2;
            *(float2*)&C[(size_t)row0 * N + col]       = make_float2(acc[a][n][0], acc[a][n][1]);
            *(float2*)&C[(size_t)(row0 + 8) * N + col] = make_float2(acc[a][n][2], acc[a][n][3]);
        }
    }
}

// ---------------------------------------------------------------------------
// Tensor-core causal flash attention, bf16 hi/lo split, KB=128 K-tiles,
// cp.async double-buffered (2 x 64KB stages).
// Stage layout (bytes): Khi@0, Klo@16K, Vhi@32K, Vlo@48K. XOR swizzle.
// ---------------------------------------------------------------------------
__device__ __forceinline__ void attn_prefetch(uint32_t dstbase,
                                              const __nv_bfloat16* gkv,
                                              int krow0, int tid)
{
#pragma unroll
    for (int j = 0; j < 16; j++) {
        int c = tid + j * 256;            // 0..4095
        int m = c >> 10;                  // matrix 0..3
        int w = c & 1023;
        int r = w >> 3, sg = w & 7;
        uint32_t off = (uint32_t)(m * 16384) +
                       (uint32_t)(r * 64 + ((sg ^ (r & 7)) * 8)) * 2;
        cp16(dstbase + off, gkv + (size_t)m * KV_MS + (size_t)(krow0 + r) * DK + sg * 8);
    }
}

__global__ void __launch_bounds__(256, 1) attn_tc(
    const float* __restrict__ qkv, __nv_bfloat16* __restrict__ atte)
{
    extern __shared__ __nv_bfloat16 sm[];
    const uint32_t sbase = (uint32_t)__cvta_generic_to_shared(sm);

    const int b = blockIdx.z, h = blockIdx.y;
    const int qt = (int)(gridDim.x - 1 - blockIdx.x);   // heavy tiles first
    const int q0 = qt * 128;
    const int tid = threadIdx.x;
    const int lane = tid & 31, warp = tid >> 5;

    const __nv_bfloat16* gkv = g_kv + ((size_t)(b * NHEADS + h)) * SEQ * DK;

    // --- Stage Q (pre-scaled by 1/8) into stage0: hi@[0,16KB), lo@[16KB,32KB)
    for (int e = tid; e < 1024; e += 256) {
        int r = e >> 3, sg = e & 7;
        const float* gq = qkv + ((size_t)(b * SEQ + q0 + r)) * QKV_N + h * DK + sg * 8;
        float4 f0 = *(const float4*)gq;
        float4 f1 = *(const float4*)(gq + 4);
        f0.x *= 0.125f; f0.y *= 0.125f; f0.z *= 0.125f; f0.w *= 0.125f;
        f1.x *= 0.125f; f1.y *= 0.125f; f1.z *= 0.125f; f1.w *= 0.125f;
        int off = r * 64 + ((sg ^ (r & 7)) * 8);
        cvt_store8(sm + off, sm + 8192 + off, f0, f1);
    }
    __syncthreads();

    // prefetch tile 0 -> stage 1
    attn_prefetch(sbase + 65536, gkv, 0, tid);
    asm volatile("cp.async.commit_group;");

    // --- Q fragments into registers (reads stage0)
    uint32_t qh[4][4], ql[4][4];
    {
        const int r = warp * 16 + (lane & 15);
        const int sgx = lane >> 4;
#pragma unroll
        for (int ks = 0; ks < 4; ks++) {
            int sg = (2 * ks + sgx) ^ (r & 7);
            uint32_t ad = sbase + (uint32_t)(r * 64 + sg * 8) * 2;
            ldm_x4(qh[ks][0], qh[ks][1], qh[ks][2], qh[ks][3], ad);
            ldm_x4(ql[ks][0], ql[ks][1], ql[ks][2], ql[ks][3], ad + 16384);
        }
    }
    __syncthreads();   // stage0 free for prefetch of tile 1

    float o[8][4];
#pragma unroll
    for (int t = 0; t < 8; t++) { o[t][0]=0.f; o[t][1]=0.f; o[t][2]=0.f; o[t][3]=0.f; }
    float m0 = -1e30f, m1 = -1e30f, l0 = 0.f, l1 = 0.f;

    for (int kt = 0; kt <= qt; kt++) {
        const int kbase = kt * 128;
        if (kt + 1 <= qt) {
            attn_prefetch(sbase + (uint32_t)(kt & 1) * 65536, gkv, kbase + 128, tid);
            asm volatile("cp.async.commit_group;");
            asm volatile("cp.async.wait_group 1;");
        } else {
            asm volatile("cp.async.wait_group 0;");
        }
        __syncthreads();
        const uint32_t sstage = sbase + (uint32_t)((kt + 1) & 1) * 65536;

        // ---- S = Q K^T (3-term split), 128 keys
        float s[16][4];
#pragma unroll
        for (int t = 0; t < 16; t++) { s[t][0]=0.f; s[t][1]=0.f; s[t][2]=0.f; s[t][3]=0.f; }

#pragma unroll
        for (int kk = 0; kk < 4; kk++) {
#pragma unroll
            for (int np = 0; np < 8; np++) {
                int krow = np * 16 + (lane & 7) + (((lane >> 4) & 1) << 3);
                int ksg = (2 * kk + ((lane >> 3) & 1)) ^ (krow & 7);
                uint32_t ad = sstage + (uint32_t)(krow * 64 + ksg * 8) * 2;
                uint32_t bh0, bh1, bh2, bh3, bl0, bl1, bl2, bl3;
                ldm_x4(bh0, bh1, bh2, bh3, ad);
                ldm_x4(bl0, bl1, bl2, bl3, ad + 16384);
                uint32_t bb[2];
                bb[0] = bh0; bb[1] = bh1;
                mma16816(s[2*np],   qh[kk], bb);
                mma16816(s[2*np],   ql[kk], bb);
                bb[0] = bh2; bb[1] = bh3;
                mma16816(s[2*np+1], qh[kk], bb);
                mma16816(s[2*np+1], ql[kk], bb);
                bb[0] = bl0; bb[1] = bl1;
                mma16816(s[2*np],   qh[kk], bb);
                bb[0] = bl2; bb[1] = bl3;
                mma16816(s[2*np+1], qh[kk], bb);
            }
        }

        // ---- causal mask on the diagonal tile
        const int rg0 = q0 + warp * 16 + (lane >> 2);
        if (kt == qt) {
#pragma unroll
            for (int nt = 0; nt < 16; nt++) {
                int c0 = kbase + nt * 8 + 2 * (lane & 3);
                if (c0     > rg0)     s[nt][0] = -1e30f;
                if (c0 + 1 > rg0)     s[nt][1] = -1e30f;
                if (c0     > rg0 + 8) s[nt][2] = -1e30f;
                if (c0 + 1 > rg0 + 8) s[nt][3] = -1e30f;
            }
        }

        // ---- online softmax (rows rg0, rg0+8)
        float mx0 = -1e30f, mx1 = -1e30f;
#pragma unroll
        for (int nt = 0; nt < 16; nt++) {
            mx0 = fmaxf(mx0, fmaxf(s[nt][0], s[nt][1]));
            mx1 = fmaxf(mx1, fmaxf(s[nt][2], s[nt][3]));
        }
        mx0 = fmaxf(mx0, __shfl_xor_sync(0xffffffffu, mx0, 1));
        mx0 = fmaxf(mx0, __shfl_xor_sync(0xffffffffu, mx0, 2));
        mx1 = fmaxf(mx1, __shfl_xor_sync(0xffffffffu, mx1, 1));
        mx1 = fmaxf(mx1, __shfl_xor_sync(0xffffffffu, mx1, 2));
        float mn0 = fmaxf(m0, mx0), mn1 = fmaxf(m1, mx1);
        float cr0 = __expf(m0 - mn0), cr1 = __expf(m1 - mn1);
        m0 = mn0; m1 = mn1;
        float sum0 = 0.f, sum1 = 0.f;
#pragma unroll
        for (int nt = 0; nt < 16; nt++) {
            s[nt][0] = __expf(s[nt][0] - mn0);
            s[nt][1] = __expf(s[nt][1] - mn0);
            s[nt][2] = __expf(s[nt][2] - mn1);
            s[nt][3] = __expf(s[nt][3] - mn1);
            sum0 += s[nt][0] + s[nt][1];
            sum1 += s[nt][2] + s[nt][3];
        }
        sum0 += __shfl_xor_sync(0xffffffffu, sum0, 1);
        sum0 += __shfl_xor_sync(0xffffffffu, sum0, 2);
        sum1 += __shfl_xor_sync(0xffffffffu, sum1, 1);
        sum1 += __shfl_xor_sync(0xffffffffu, sum1, 2);
        l0 = l0 * cr0 + sum0;
        l1 = l1 * cr1 + sum1;
#pragma unroll
        for (int t = 0; t < 8; t++) {
            o[t][0] *= cr0; o[t][1] *= cr0; o[t][2] *= cr1; o[t][3] *= cr1;
        }

        // ---- O += P V (3-term split), V tile 128 rows
#pragma unroll
        for (int ks = 0; ks < 8; ks++) {
            uint32_t ah[4], al[4];
            pack_hilo(s[2*ks][0],   s[2*ks][1],   ah[0], al[0]);
            pack_hilo(s[2*ks][2],   s[2*ks][3],   ah[1], al[1]);
            pack_hilo(s[2*ks+1][0], s[2*ks+1][1], ah[2], al[2]);
            pack_hilo(s[2*ks+1][2], s[2*ks+1][3], ah[3], al[3]);
#pragma unroll
            for (int cp = 0; cp < 4; cp++) {
                int vrow = ks * 16 + (lane & 15);
                int vsg = (2 * cp + (lane >> 4)) ^ (vrow & 7);
                uint32_t va = sstage + 32768 + (uint32_t)(vrow * 64 + vsg * 8) * 2;
                uint32_t vh0, vh1, vh2, vh3, vl0, vl1, vl2, vl3;
                ldm_x4_t(vh0, vh1, vh2, vh3, va);
                ldm_x4_t(vl0, vl1, vl2, vl3, va + 16384);
                uint32_t bb[2];
                bb[0] = vh0; bb[1] = vh1;
                mma16816(o[2*cp],   ah, bb);
                mma16816(o[2*cp],   al, bb);
                bb[0] = vl0; bb[1] = vl1;
                mma16816(o[2*cp],   ah, bb);
                bb[0] = vh2; bb[1] = vh3;
                mma16816(o[2*cp+1], ah, bb);
                mma16816(o[2*cp+1], al, bb);
                bb[0] = vl2; bb[1] = vl3;
                mma16816(o[2*cp+1], ah, bb);
            }
        }
        __syncthreads();   // done reading this stage
    }

    const float inv0 = 1.f / l0, inv1 = 1.f / l1;
    const int rg0 = q0 + warp * 16 + (lane >> 2);
    const size_t ro0 = (size_t)(b * SEQ + rg0) * KEXT;
    const size_t ro1 = (size_t)(b * SEQ + rg0 + 8) * KEXT;
#pragma unroll
    for (int nt = 0; nt < 8; nt++) {
        int col = h * DK + nt * 8 + 2 * (lane & 3);
        uint32_t hi, lo;
        pack_hilo(o[nt][0] * inv0, o[nt][1] * inv0, hi, lo);
        *(uint32_t*)(atte + ro0 + col)            = hi;
        *(uint32_t*)(atte + ro0 + DMODEL + col)   = lo;
        *(uint32_t*)(atte + ro0 + 2*DMODEL + col) = hi;
        pack_hilo(o[nt][2] * inv1, o[nt][3] * inv1, hi, lo);
        *(uint32_t*)(atte + ro1 + col)            = hi;
        *(uint32_t*)(atte + ro1 + DMODEL + col)   = lo;
        *(uint32_t*)(atte + ro1 + 2*DMODEL + col) = hi;
    }
}

// ---------------------------------------------------------------------------
// kernel_launch
// ---------------------------------------------------------------------------
extern "C" void kernel_launch(void* const* d_in, const int* in_sizes, int n_in,
                              void* d_out, int out_size)
{
    const float* x     = (const float*)d_in[0];   // [2, 2048, 1024]
    const float* W_qkv = (const float*)d_in[1];   // [3072, 1024]
    const float* W_out = (const float*)d_in[2];   // [1024, 1024]
    float* out = (float*)d_out;                   // [2, 2048, 1024]

    float* qkv_ptr = nullptr;
    __nv_bfloat16 *xe, *wqkve, *wute, *atte;
    cudaGetSymbolAddress((void**)&qkv_ptr, g_qkv);
    cudaGetSymbolAddress((void**)&xe,    g_xe);
    cudaGetSymbolAddress((void**)&wqkve, g_wqkve);
    cudaGetSymbolAddress((void**)&wute,  g_wute);
    cudaGetSymbolAddress((void**)&atte,  g_atte);

    cudaFuncSetAttribute(gemm_bf16, cudaFuncAttributeMaxDynamicSharedMemorySize, 3 * GSTAGE_BYTES);
    cudaFuncSetAttribute(attn_tc,   cudaFuncAttributeMaxDynamicSharedMemorySize, 131072);

    // 0) split conversions (inputs)
    {
        size_t tx_ = (size_t)MTOT * DMODEL;
        conv_split<1><<<(unsigned)((tx_/4 + 255)/256), 256>>>(x, xe, DMODEL, tx_);
        size_t tw = (size_t)QKV_N * DMODEL;
        conv_split<0><<<(unsigned)((tw/4 + 255)/256), 256>>>(W_qkv, wqkve, DMODEL, tw);
        size_t tu = (size_t)DMODEL * DMODEL;
        conv_split<0><<<(unsigned)((tu/4 + 255)/256), 256>>>(W_out, wute, DMODEL, tu);
    }
    // 1) QKV projection: [4096,3072] f32
    {
        dim3 grid(QKV_N / 128, MTOT / 128);
        gemm_bf16<<<grid, 256, 3 * GSTAGE_BYTES>>>(xe, wqkve, qkv_ptr, QKV_N);
    }
    // 1b) pre-convert K/V to hi/lo bf16 into g_kv
    {
        size_t tot = (size_t)MTOT * DMODEL;
        conv_qkv<<<(unsigned)((tot/4 + 255)/256), 256>>>(qkv_ptr);
    }
    // 2) tensor-core causal flash attention -> g_atte (bf16 split layout)
    {
        dim3 grid(SEQ / 128, NHEADS, BATCH);
        attn_tc<<<grid, 256, 131072>>>(qkv_ptr, atte);
    }
    // 3) output projection -> d_out
    {
        dim3 grid(DMODEL / 128, MTOT / 128);
        gemm_bf16<<<grid, 256, 3 * GSTAGE_BYTES>>>(atte, wute, out, DMODEL);
    }
}

// round 10
// speedup vs baseline: 1.2928x; 1.0710x over previous
#include <cuda_runtime.h>
#include <cuda_bf16.h>
#include <math.h>
#include <stdint.h>

// Problem constants
#define BATCH 2
#define SEQ   2048
#define DMODEL 1024
#define NHEADS 16
#define DK    64
#define MTOT  (BATCH*SEQ)          // 4096
#define QKV_N (3*DMODEL)           // 3072
#define KE2   (2*DMODEL)           // 2048: [hi | lo] layout width
#define KV_MS ((size_t)MTOT * DMODEL)   // per-matrix stride in g_kv

// Scratch (device globals — no allocation allowed)
__device__ float g_qkv[(size_t)MTOT * QKV_N];             // f32 qkv
__device__ __nv_bfloat16 g_xe   [(size_t)MTOT  * KE2];    // x      [hi|lo]
__device__ __nv_bfloat16 g_wqkve[(size_t)QKV_N * KE2];    // W_qkv  [hi|lo]
__device__ __nv_bfloat16 g_wute [(size_t)DMODEL* KE2];    // W_out  [hi|lo]
__device__ __nv_bfloat16 g_atte [(size_t)MTOT  * KE2];    // attn out [hi|lo]
// pre-converted K/V: [m][b*h][s][dk], m = {Khi, Klo, Vhi, Vlo}
__device__ __nv_bfloat16 g_kv[(size_t)4 * MTOT * DMODEL];

// ---------------------------------------------------------------------------
// helpers
// ---------------------------------------------------------------------------
__device__ __forceinline__ void pack_hilo(float a, float b, uint32_t& hi, uint32_t& lo)
{
    __nv_bfloat16 ha = __float2bfloat16_rn(a), hb = __float2bfloat16_rn(b);
    __nv_bfloat162 h; h.x = ha; h.y = hb;
    __nv_bfloat162 l;
    l.x = __float2bfloat16_rn(a - __bfloat162float(ha));
    l.y = __float2bfloat16_rn(b - __bfloat162float(hb));
    hi = *(uint32_t*)&h; lo = *(uint32_t*)&l;
}

__device__ __forceinline__ void ldm_x4(uint32_t& r0, uint32_t& r1, uint32_t& r2, uint32_t& r3,
                                       uint32_t addr)
{
    asm volatile("ldmatrix.sync.aligned.m8n8.x4.shared.b16 {%0,%1,%2,%3}, [%4];"
                 : "=r"(r0), "=r"(r1), "=r"(r2), "=r"(r3) : "r"(addr));
}

__device__ __forceinline__ void ldm_x4_t(uint32_t& r0, uint32_t& r1, uint32_t& r2, uint32_t& r3,
                                         uint32_t addr)
{
    asm volatile("ldmatrix.sync.aligned.m8n8.x4.trans.shared.b16 {%0,%1,%2,%3}, [%4];"
                 : "=r"(r0), "=r"(r1), "=r"(r2), "=r"(r3) : "r"(addr));
}

__device__ __forceinline__ void mma16816(float* d, const uint32_t* a, const uint32_t* b)
{
    asm volatile(
        "mma.sync.aligned.m16n8k16.row.col.f32.bf16.bf16.f32 "
        "{%0,%1,%2,%3}, {%4,%5,%6,%7}, {%8,%9}, {%0,%1,%2,%3};"
        : "+f"(d[0]), "+f"(d[1]), "+f"(d[2]), "+f"(d[3])
        : "r"(a[0]), "r"(a[1]), "r"(a[2]), "r"(a[3]), "r"(b[0]), "r"(b[1]));
}

__device__ __forceinline__ void cp16(uint32_t saddr, const void* gptr)
{
    asm volatile("cp.async.cg.shared.global [%0], [%1], 16;" :: "r"(saddr), "l"(gptr));
}

__device__ __forceinline__ void cvt_store8(__nv_bfloat16* dhi, __nv_bfloat16* dlo,
                                           float4 f0, float4 f1)
{
    uint32_t h0,h1,h2,h3,l0,l1,l2,l3;
    pack_hilo(f0.x, f0.y, h0, l0);
    pack_hilo(f0.z, f0.w, h1, l1);
    pack_hilo(f1.x, f1.y, h2, l2);
    pack_hilo(f1.z, f1.w, h3, l3);
    *(uint4*)dhi = make_uint4(h0, h1, h2, h3);
    *(uint4*)dlo = make_uint4(l0, l1, l2, l3);
}

// ---------------------------------------------------------------------------
// Split-conversion: f32 [R,K] -> bf16 [R,2K]  ([k]=hi, [K+k]=lo)
// ---------------------------------------------------------------------------
__global__ void conv_split(const float* __restrict__ in, __nv_bfloat16* __restrict__ out,
                           int K, size_t total)
{
    size_t idx = ((size_t)blockIdx.x * blockDim.x + threadIdx.x) * 4;
    if (idx >= total) return;
    int r = (int)(idx / K);
    int k = (int)(idx % K);
    float4 v = *(const float4*)(in + idx);
    uint32_t hi01, hi23, lo01, lo23;
    pack_hilo(v.x, v.y, hi01, lo01);
    pack_hilo(v.z, v.w, hi23, lo23);
    __nv_bfloat16* o = out + (size_t)r * (2 * K) + k;
    *(uint32_t*)(o + 0) = hi01;  *(uint32_t*)(o + 2) = hi23;
    *(uint32_t*)(o + K + 0) = lo01; *(uint32_t*)(o + K + 2) = lo23;
}

// ---------------------------------------------------------------------------
// conv_qkv: pre-convert K and V slabs of g_qkv to hi/lo bf16 into g_kv.
// ---------------------------------------------------------------------------
__global__ void conv_qkv(const float* __restrict__ qkv)
{
    size_t idx = ((size_t)blockIdx.x * blockDim.x + threadIdx.x) * 4;   // over MTOT*DMODEL
    if (idx >= (size_t)MTOT * DMODEL) return;
    int r = (int)(idx >> 10);          // row in [0,4096)
    int c = (int)(idx & 1023);         // col in [0,1024)
    int h = c >> 6, d = c & 63;
    int b = r >> 11, s = r & 2047;
    size_t off = (((size_t)(b * NHEADS + h)) * SEQ + s) * DK + d;

    const float* src = qkv + (size_t)r * QKV_N + DMODEL + c;
    float4 kv = *(const float4*)src;
    float4 vv = *(const float4*)(src + DMODEL);
    uint32_t h01, h23, l01, l23;
    pack_hilo(kv.x, kv.y, h01, l01); pack_hilo(kv.z, kv.w, h23, l23);
    *(uint32_t*)&g_kv[0 * KV_MS + off] = h01; *(uint32_t*)&g_kv[0 * KV_MS + off + 2] = h23;
    *(uint32_t*)&g_kv[1 * KV_MS + off] = l01; *(uint32_t*)&g_kv[1 * KV_MS + off + 2] = l23;
    pack_hilo(vv.x, vv.y, h01, l01); pack_hilo(vv.z, vv.w, h23, l23);
    *(uint32_t*)&g_kv[2 * KV_MS + off] = h01; *(uint32_t*)&g_kv[2 * KV_MS + off + 2] = h23;
    *(uint32_t*)&g_kv[3 * KV_MS + off] = l01; *(uint32_t*)&g_kv[3 * KV_MS + off + 2] = l23;
}

// ---------------------------------------------------------------------------
// bf16 tensor-core GEMM with 3-term fragment reuse:
//   C = Ahi*Bhi^T + Alo*Bhi^T + Ahi*Blo^T   (fp32 accumulate)
// A,B stored [rows][2K] = [hi|lo]. 128x128 block, BK=32 real-K per step,
// 32 steps, 3-stage cp.async ring (32KB/stage), one __syncthreads per step.
// Stage layout: [Ahi 8K][Alo 8K][Bhi 8K][Blo 8K].
// ---------------------------------------------------------------------------
#define GSTAGE_BYTES 32768

__global__ void __launch_bounds__(256, 2) gemm_bf16(
    const __nv_bfloat16* __restrict__ A, const __nv_bfloat16* __restrict__ B,
    float* __restrict__ C, int N)
{
    extern __shared__ __nv_bfloat16 gsm[];
    const uint32_t sbase = (uint32_t)__cvta_generic_to_shared(gsm);

    const int tid  = threadIdx.x;
    const int lane = tid & 31;
    const int warp = tid >> 5;
    const int wr = warp >> 2;
    const int wc = warp & 3;
    const int mBase = blockIdx.y * 128;
    const int nBase = blockIdx.x * 128;

    const int lrow = tid >> 2;
    const int lseg = tid & 3;
    const uint32_t swz0 = (uint32_t)(lrow * 32 + ((lseg ^ ((lrow >> 1) & 3)) * 8)) * 2;
    const uint32_t swz1 = (uint32_t)((lrow + 64) * 32 + ((lseg ^ (((lrow + 64) >> 1) & 3)) * 8)) * 2;
    const __nv_bfloat16* gA0 = A + (size_t)(mBase + lrow)      * KE2 + lseg * 8;
    const __nv_bfloat16* gA1 = A + (size_t)(mBase + lrow + 64) * KE2 + lseg * 8;
    const __nv_bfloat16* gB0 = B + (size_t)(nBase + lrow)      * KE2 + lseg * 8;
    const __nv_bfloat16* gB1 = B + (size_t)(nBase + lrow + 64) * KE2 + lseg * 8;

    const int arow = wr * 64 + (lane & 15);
    const int aseg = (lane >> 4) & 1;
    const int brow = wc * 32 + (lane & 7) + (((lane >> 4) & 1) << 3);
    const int bseg = (lane >> 3) & 1;

    float acc[4][4][4];
#pragma unroll
    for (int a = 0; a < 4; a++)
#pragma unroll
        for (int n = 0; n < 4; n++)
#pragma unroll
            for (int i = 0; i < 4; i++) acc[a][n][i] = 0.f;

    const int NSTEP = DMODEL / 32;     // 32 real-K steps

    // prologue: stages 0,1  ([Ahi][Alo][Bhi][Blo] per stage)
#pragma unroll
    for (int s = 0; s < 2; s++) {
        const uint32_t st = sbase + s * GSTAGE_BYTES;
        const int k0 = s * 32;
        cp16(st +          swz0, gA0 + k0);           cp16(st +          swz1, gA1 + k0);
        cp16(st +  8192 + swz0, gA0 + DMODEL + k0);   cp16(st +  8192 + swz1, gA1 + DMODEL + k0);
        cp16(st + 16384 + swz0, gB0 + k0);            cp16(st + 16384 + swz1, gB1 + k0);
        cp16(st + 24576 + swz0, gB0 + DMODEL + k0);   cp16(st + 24576 + swz1, gB1 + DMODEL + k0);
        asm volatile("cp.async.commit_group;");
    }

    int cur = 0, nxt = 2;
    for (int t = 0; t < NSTEP; t++) {
        if (t + 1 < NSTEP) asm volatile("cp.async.wait_group 1;");
        else               asm volatile("cp.async.wait_group 0;");
        __syncthreads();

        if (t + 2 < NSTEP) {
            const uint32_t st = sbase + nxt * GSTAGE_BYTES;
            const int k0 = (t + 2) * 32;
            cp16(st +          swz0, gA0 + k0);           cp16(st +          swz1, gA1 + k0);
            cp16(st +  8192 + swz0, gA0 + DMODEL + k0);   cp16(st +  8192 + swz1, gA1 + DMODEL + k0);
            cp16(st + 16384 + swz0, gB0 + k0);            cp16(st + 16384 + swz1, gB1 + k0);
            cp16(st + 24576 + swz0, gB0 + DMODEL + k0);   cp16(st + 24576 + swz1, gB1 + DMODEL + k0);
            asm volatile("cp.async.commit_group;");
        }

        const uint32_t stg = sbase + cur * GSTAGE_BYTES;

#pragma unroll
        for (int kk = 0; kk < 2; kk++) {
            // --- load Ahi fragments
            uint32_t ah[4][4];
#pragma unroll
            for (int a = 0; a < 4; a++) {
                int r = arow + a * 16;
                int seg = (kk * 2 + aseg) ^ ((r >> 1) & 3);
                ldm_x4(ah[a][0], ah[a][1], ah[a][2], ah[a][3],
                       stg + (uint32_t)(r * 32 + seg * 8) * 2);
            }
            // --- load Bhi fragments
            uint32_t bh[4][2];
#pragma unroll
            for (int p = 0; p < 2; p++) {
                int n = brow + p * 16;
                int seg = (kk * 2 + bseg) ^ ((n >> 1) & 3);
                uint32_t r0, r1, r2, r3;
                ldm_x4(r0, r1, r2, r3, stg + 16384 + (uint32_t)(n * 32 + seg * 8) * 2);
                bh[p * 2 + 0][0] = r0; bh[p * 2 + 0][1] = r1;
                bh[p * 2 + 1][0] = r2; bh[p * 2 + 1][1] = r3;
            }
            // term 1: Ahi * Bhi
#pragma unroll
            for (int a = 0; a < 4; a++)
#pragma unroll
                for (int n = 0; n < 4; n++)
                    mma16816(acc[a][n], ah[a], bh[n]);

            // --- load Alo, term 2: Alo * Bhi
            {
                uint32_t al[4][4];
#pragma unroll
                for (int a = 0; a < 4; a++) {
                    int r = arow + a * 16;
                    int seg = (kk * 2 + aseg) ^ ((r >> 1) & 3);
                    ldm_x4(al[a][0], al[a][1], al[a][2], al[a][3],
                           stg + 8192 + (uint32_t)(r * 32 + seg * 8) * 2);
                }
#pragma unroll
                for (int a = 0; a < 4; a++)
#pragma unroll
                    for (int n = 0; n < 4; n++)
                        mma16816(acc[a][n], al[a], bh[n]);
            }

            // --- load Blo, term 3: Ahi * Blo
            {
                uint32_t bl[4][2];
#pragma unroll
                for (int p = 0; p < 2; p++) {
                    int n = brow + p * 16;
                    int seg = (kk * 2 + bseg) ^ ((n >> 1) & 3);
                    uint32_t r0, r1, r2, r3;
                    ldm_x4(r0, r1, r2, r3, stg + 24576 + (uint32_t)(n * 32 + seg * 8) * 2);
                    bl[p * 2 + 0][0] = r0; bl[p * 2 + 0][1] = r1;
                    bl[p * 2 + 1][0] = r2; bl[p * 2 + 1][1] = r3;
                }
#pragma unroll
                for (int a = 0; a < 4; a++)
#pragma unroll
                    for (int n = 0; n < 4; n++)
                        mma16816(acc[a][n], ah[a], bl[n]);
            }
        }
        cur = (cur == 2) ? 0 : cur + 1;
        nxt = (nxt == 2) ? 0 : nxt + 1;
    }

#pragma unroll
    for (int a = 0; a < 4; a++) {
        int row0 = mBase + wr * 64 + a * 16 + (lane >> 2);
#pragma unroll
        for (int n = 0; n < 4; n++) {
            int col = nBase + wc * 32 + n * 8 + (lane & 3) * 2;
            *(float2*)&C[(size_t)row0 * N + col]       = make_float2(acc[a][n][0], acc[a][n][1]);
            *(float2*)&C[(size_t)(row0 + 8) * N + col] = make_float2(acc[a][n][2], acc[a][n][3]);
        }
    }
}

// ---------------------------------------------------------------------------
// Tensor-core causal flash attention, bf16 hi/lo split, KB=128 K-tiles,
// cp.async double-buffered (2 x 64KB stages). (structure from R9)
// Stage layout (bytes): Khi@0, Klo@16K, Vhi@32K, Vlo@48K. XOR swizzle.
// ---------------------------------------------------------------------------
__device__ __forceinline__ void attn_prefetch(uint32_t dstbase,
                                              const __nv_bfloat16* gkv,
                                              int krow0, int tid)
{
#pragma unroll
    for (int j = 0; j < 16; j++) {
        int c = tid + j * 256;            // 0..4095
        int m = c >> 10;                  // matrix 0..3
        int w = c & 1023;
        int r = w >> 3, sg = w & 7;
        uint32_t off = (uint32_t)(m * 16384) +
                       (uint32_t)(r * 64 + ((sg ^ (r & 7)) * 8)) * 2;
        cp16(dstbase + off, gkv + (size_t)m * KV_MS + (size_t)(krow0 + r) * DK + sg * 8);
    }
}

__global__ void __launch_bounds__(256, 1) attn_tc(
    const float* __restrict__ qkv, __nv_bfloat16* __restrict__ atte)
{
    extern __shared__ __nv_bfloat16 sm[];
    const uint32_t sbase = (uint32_t)__cvta_generic_to_shared(sm);

    const int b = blockIdx.z, h = blockIdx.y;
    const int qt = (int)(gridDim.x - 1 - blockIdx.x);   // heavy tiles first
    const int q0 = qt * 128;
    const int tid = threadIdx.x;
    const int lane = tid & 31, warp = tid >> 5;

    const __nv_bfloat16* gkv = g_kv + ((size_t)(b * NHEADS + h)) * SEQ * DK;

    // --- Stage Q (pre-scaled by 1/8) into stage0: hi@[0,16KB), lo@[16KB,32KB)
    for (int e = tid; e < 1024; e += 256) {
        int r = e >> 3, sg = e & 7;
        const float* gq = qkv + ((size_t)(b * SEQ + q0 + r)) * QKV_N + h * DK + sg * 8;
        float4 f0 = *(const float4*)gq;
        float4 f1 = *(const float4*)(gq + 4);
        f0.x *= 0.125f; f0.y *= 0.125f; f0.z *= 0.125f; f0.w *= 0.125f;
        f1.x *= 0.125f; f1.y *= 0.125f; f1.z *= 0.125f; f1.w *= 0.125f;
        int off = r * 64 + ((sg ^ (r & 7)) * 8);
        cvt_store8(sm + off, sm + 8192 + off, f0, f1);
    }
    __syncthreads();

    // prefetch tile 0 -> stage 1
    attn_prefetch(sbase + 65536, gkv, 0, tid);
    asm volatile("cp.async.commit_group;");

    // --- Q fragments into registers (reads stage0)
    uint32_t qh[4][4], ql[4][4];
    {
        const int r = warp * 16 + (lane & 15);
        const int sgx = lane >> 4;
#pragma unroll
        for (int ks = 0; ks < 4; ks++) {
            int sg = (2 * ks + sgx) ^ (r & 7);
            uint32_t ad = sbase + (uint32_t)(r * 64 + sg * 8) * 2;
            ldm_x4(qh[ks][0], qh[ks][1], qh[ks][2], qh[ks][3], ad);
            ldm_x4(ql[ks][0], ql[ks][1], ql[ks][2], ql[ks][3], ad + 16384);
        }
    }
    __syncthreads();   // stage0 free for prefetch of tile 1

    float o[8][4];
#pragma unroll
    for (int t = 0; t < 8; t++) { o[t][0]=0.f; o[t][1]=0.f; o[t][2]=0.f; o[t][3]=0.f; }
    float m0 = -1e30f, m1 = -1e30f, l0 = 0.f, l1 = 0.f;

    for (int kt = 0; kt <= qt; kt++) {
        const int kbase = kt * 128;
        if (kt + 1 <= qt) {
            attn_prefetch(sbase + (uint32_t)(kt & 1) * 65536, gkv, kbase + 128, tid);
            asm volatile("cp.async.commit_group;");
            asm volatile("cp.async.wait_group 1;");
        } else {
            asm volatile("cp.async.wait_group 0;");
        }
        __syncthreads();
        const uint32_t sstage = sbase + (uint32_t)((kt + 1) & 1) * 65536;

        // ---- S = Q K^T (3-term split), 128 keys
        float s[16][4];
#pragma unroll
        for (int t = 0; t < 16; t++) { s[t][0]=0.f; s[t][1]=0.f; s[t][2]=0.f; s[t][3]=0.f; }

#pragma unroll
        for (int kk = 0; kk < 4; kk++) {
#pragma unroll
            for (int np = 0; np < 8; np++) {
                int krow = np * 16 + (lane & 7) + (((lane >> 4) & 1) << 3);
                int ksg = (2 * kk + ((lane >> 3) & 1)) ^ (krow & 7);
                uint32_t ad = sstage + (uint32_t)(krow * 64 + ksg * 8) * 2;
                uint32_t bh0, bh1, bh2, bh3, bl0, bl1, bl2, bl3;
                ldm_x4(bh0, bh1, bh2, bh3, ad);
                ldm_x4(bl0, bl1, bl2, bl3, ad + 16384);
                uint32_t bb[2];
                bb[0] = bh0; bb[1] = bh1;
                mma16816(s[2*np],   qh[kk], bb);
                mma16816(s[2*np],   ql[kk], bb);
                bb[0] = bh2; bb[1] = bh3;
                mma16816(s[2*np+1], qh[kk], bb);
                mma16816(s[2*np+1], ql[kk], bb);
                bb[0] = bl0; bb[1] = bl1;
                mma16816(s[2*np],   qh[kk], bb);
                bb[0] = bl2; bb[1] = bl3;
                mma16816(s[2*np+1], qh[kk], bb);
            }
        }

        // ---- causal mask on the diagonal tile
        const int rg0 = q0 + warp * 16 + (lane >> 2);
        if (kt == qt) {
#pragma unroll
            for (int nt = 0; nt < 16; nt++) {
                int c0 = kbase + nt * 8 + 2 * (lane & 3);
                if (c0     > rg0)     s[nt][0] = -1e30f;
                if (c0 + 1 > rg0)     s[nt][1] = -1e30f;
                if (c0     > rg0 + 8) s[nt][2] = -1e30f;
                if (c0 + 1 > rg0 + 8) s[nt][3] = -1e30f;
            }
        }

        // ---- online softmax (rows rg0, rg0+8)
        float mx0 = -1e30f, mx1 = -1e30f;
#pragma unroll
        for (int nt = 0; nt < 16; nt++) {
            mx0 = fmaxf(mx0, fmaxf(s[nt][0], s[nt][1]));
            mx1 = fmaxf(mx1, fmaxf(s[nt][2], s[nt][3]));
        }
        mx0 = fmaxf(mx0, __shfl_xor_sync(0xffffffffu, mx0, 1));
        mx0 = fmaxf(mx0, __shfl_xor_sync(0xffffffffu, mx0, 2));
        mx1 = fmaxf(mx1, __shfl_xor_sync(0xffffffffu, mx1, 1));
        mx1 = fmaxf(mx1, __shfl_xor_sync(0xffffffffu, mx1, 2));
        float mn0 = fmaxf(m0, mx0), mn1 = fmaxf(m1, mx1);
        float cr0 = __expf(m0 - mn0), cr1 = __expf(m1 - mn1);
        m0 = mn0; m1 = mn1;
        float sum0 = 0.f, sum1 = 0.f;
#pragma unroll
        for (int nt = 0; nt < 16; nt++) {
            s[nt][0] = __expf(s[nt][0] - mn0);
            s[nt][1] = __expf(s[nt][1] - mn0);
            s[nt][2] = __expf(s[nt][2] - mn1);
            s[nt][3] = __expf(s[nt][3] - mn1);
            sum0 += s[nt][0] + s[nt][1];
            sum1 += s[nt][2] + s[nt][3];
        }
        sum0 += __shfl_xor_sync(0xffffffffu, sum0, 1);
        sum0 += __shfl_xor_sync(0xffffffffu, sum0, 2);
        sum1 += __shfl_xor_sync(0xffffffffu, sum1, 1);
        sum1 += __shfl_xor_sync(0xffffffffu, sum1, 2);
        l0 = l0 * cr0 + sum0;
        l1 = l1 * cr1 + sum1;
#pragma unroll
        for (int t = 0; t < 8; t++) {
            o[t][0] *= cr0; o[t][1] *= cr0; o[t][2] *= cr1; o[t][3] *= cr1;
        }

        // ---- O += P V (3-term split), V tile 128 rows
#pragma unroll
        for (int ks = 0; ks < 8; ks++) {
            uint32_t ah[4], al[4];
            pack_hilo(s[2*ks][0],   s[2*ks][1],   ah[0], al[0]);
            pack_hilo(s[2*ks][2],   s[2*ks][3],   ah[1], al[1]);
            pack_hilo(s[2*ks+1][0], s[2*ks+1][1], ah[2], al[2]);
            pack_hilo(s[2*ks+1][2], s[2*ks+1][3], ah[3], al[3]);
#pragma unroll
            for (int cp = 0; cp < 4; cp++) {
                int vrow = ks * 16 + (lane & 15);
                int vsg = (2 * cp + (lane >> 4)) ^ (vrow & 7);
                uint32_t va = sstage + 32768 + (uint32_t)(vrow * 64 + vsg * 8) * 2;
                uint32_t vh0, vh1, vh2, vh3, vl0, vl1, vl2, vl3;
                ldm_x4_t(vh0, vh1, vh2, vh3, va);
                ldm_x4_t(vl0, vl1, vl2, vl3, va + 16384);
                uint32_t bb[2];
                bb[0] = vh0; bb[1] = vh1;
                mma16816(o[2*cp],   ah, bb);
                mma16816(o[2*cp],   al, bb);
                bb[0] = vl0; bb[1] = vl1;
                mma16816(o[2*cp],   ah, bb);
                bb[0] = vh2; bb[1] = vh3;
                mma16816(o[2*cp+1], ah, bb);
                mma16816(o[2*cp+1], al, bb);
                bb[0] = vl2; bb[1] = vl3;
                mma16816(o[2*cp+1], ah, bb);
            }
        }
        __syncthreads();   // done reading this stage
    }

    // ---- epilogue: write [hi|lo] 2K layout
    const float inv0 = 1.f / l0, inv1 = 1.f / l1;
    const int rg0 = q0 + warp * 16 + (lane >> 2);
    const size_t ro0 = (size_t)(b * SEQ + rg0) * KE2;
    const size_t ro1 = (size_t)(b * SEQ + rg0 + 8) * KE2;
#pragma unroll
    for (int nt = 0; nt < 8; nt++) {
        int col = h * DK + nt * 8 + 2 * (lane & 3);
        uint32_t hi, lo;
        pack_hilo(o[nt][0] * inv0, o[nt][1] * inv0, hi, lo);
        *(uint32_t*)(atte + ro0 + col)          = hi;
        *(uint32_t*)(atte + ro0 + DMODEL + col) = lo;
        pack_hilo(o[nt][2] * inv1, o[nt][3] * inv1, hi, lo);
        *(uint32_t*)(atte + ro1 + col)          = hi;
        *(uint32_t*)(atte + ro1 + DMODEL + col) = lo;
    }
}

// ---------------------------------------------------------------------------
// kernel_launch
// ---------------------------------------------------------------------------
extern "C" void kernel_launch(void* const* d_in, const int* in_sizes, int n_in,
                              void* d_out, int out_size)
{
    const float* x     = (const float*)d_in[0];   // [2, 2048, 1024]
    const float* W_qkv = (const float*)d_in[1];   // [3072, 1024]
    const float* W_out = (const float*)d_in[2];   // [1024, 1024]
    float* out = (float*)d_out;                   // [2, 2048, 1024]

    float* qkv_ptr = nullptr;
    __nv_bfloat16 *xe, *wqkve, *wute, *atte;
    cudaGetSymbolAddress((void**)&qkv_ptr, g_qkv);
    cudaGetSymbolAddress((void**)&xe,    g_xe);
    cudaGetSymbolAddress((void**)&wqkve, g_wqkve);
    cudaGetSymbolAddress((void**)&wute,  g_wute);
    cudaGetSymbolAddress((void**)&atte,  g_atte);

    cudaFuncSetAttribute(gemm_bf16, cudaFuncAttributeMaxDynamicSharedMemorySize, 3 * GSTAGE_BYTES);
    cudaFuncSetAttribute(attn_tc,   cudaFuncAttributeMaxDynamicSharedMemorySize, 131072);

    // 0) split conversions (inputs) -> [hi|lo] 2K layout
    {
        size_t tx_ = (size_t)MTOT * DMODEL;
        conv_split<<<(unsigned)((tx_/4 + 255)/256), 256>>>(x, xe, DMODEL, tx_);
        size_t tw = (size_t)QKV_N * DMODEL;
        conv_split<<<(unsigned)((tw/4 + 255)/256), 256>>>(W_qkv, wqkve, DMODEL, tw);
        size_t tu = (size_t)DMODEL * DMODEL;
        conv_split<<<(unsigned)((tu/4 + 255)/256), 256>>>(W_out, wute, DMODEL, tu);
    }
    // 1) QKV projection: [4096,3072] f32
    {
        dim3 grid(QKV_N / 128, MTOT / 128);
        gemm_bf16<<<grid, 256, 3 * GSTAGE_BYTES>>>(xe, wqkve, qkv_ptr, QKV_N);
    }
    // 1b) pre-convert K/V to hi/lo bf16 into g_kv
    {
        size_t tot = (size_t)MTOT * DMODEL;
        conv_qkv<<<(unsigned)((tot/4 + 255)/256), 256>>>(qkv_ptr);
    }
    // 2) tensor-core causal flash attention -> g_atte ([hi|lo] layout)
    {
        dim3 grid(SEQ / 128, NHEADS, BATCH);
        attn_tc<<<grid, 256, 131072>>>(qkv_ptr, atte);
    }
    // 3) output projection -> d_out
    {
        dim3 grid(DMODEL / 128, MTOT / 128);
        gemm_bf16<<<grid, 256, 3 * GSTAGE_BYTES>>>(atte, wute, out, DMODEL);
    }
}